// round 11
// baseline (speedup 1.0000x reference)
#include <cuda_runtime.h>
#include <cuda_bf16.h>
#include <math.h>
#include <cstdint>

// ---------------------------------------------------------------------------
// VideoAttention: b=2, t=8, C=768, h=w=16 -> hw=256, S=2048, heads=12, c=64
//   K1 norm_k    : EDM2 MP weight norm -> pre-split tf32 hi/lo weight planes
//   K2 xsplit    : x -> tf32 hi/lo planes
//   K3 gemm_f3<0>: 3xTF32 HMMA GEMM -> q,k fp32; V pre-split + transposed [bm][c][s]
//   K4 rope_k    : rotary over frame index; k -> tf32 hi/lo split
//   K5 flash_tc  : block-causal flash attention, 3xTF32 HMMA, ldmatrix operands,
//                  SPLIT accumulators (hi-term / correction-term) for 2x MMA ILP
//   K6 gemm_f3<1>: 3xTF32 HMMA proj GEMM + mp_sum residual -> out
// ---------------------------------------------------------------------------

#define NB   2
#define NT   8
#define NM   12
#define HD   64
#define C3   2304
#define CDIM 768
#define SLEN 2048
#define BT   16
#define XSTRIDE 196608   // 768*256

__device__ float g_q[NB * NM * SLEN * HD];
__device__ float g_k[NB * NM * SLEN * HD];
__device__ uint32_t g_kh[NB * NM * SLEN * HD], g_kl[NB * NM * SLEN * HD];
__device__ uint32_t g_vh[NB * NM * SLEN * HD], g_vl[NB * NM * SLEN * HD]; // [bm][c][s]
__device__ uint32_t g_wqh[C3 * CDIM],  g_wql[C3 * CDIM];
__device__ uint32_t g_wph[CDIM * CDIM], g_wpl[CDIM * CDIM];
__device__ uint32_t g_xh[BT * CDIM * 256], g_xl[BT * CDIM * 256];
__device__ uint32_t g_yh[BT * CDIM * 256], g_yl[BT * CDIM * 256];

// ======================= PTX helpers ===================
__device__ __forceinline__ uint32_t smem_to_u32(const void* p) {
    uint32_t a;
    asm("{ .reg .u64 t; cvta.to.shared.u64 t, %1; cvt.u32.u64 %0, t; }" : "=r"(a) : "l"(p));
    return a;
}
__device__ __forceinline__ uint32_t lds_u32(uint32_t addr) {
    uint32_t v;
    asm volatile("ld.shared.b32 %0, [%1];" : "=r"(v) : "r"(addr));
    return v;
}
__device__ __forceinline__ void sts_u32(uint32_t addr, uint32_t v) {
    asm volatile("st.shared.b32 [%0], %1;" :: "r"(addr), "r"(v));
}
__device__ __forceinline__ void sts64(uint32_t addr, uint32_t a, uint32_t b) {
    asm volatile("st.shared.v2.b32 [%0], {%1,%2};" :: "r"(addr), "r"(a), "r"(b));
}
__device__ __forceinline__ void cp16(uint32_t dst, const void* src) {
    asm volatile("cp.async.cg.shared.global [%0], [%1], 16;" :: "r"(dst), "l"(src));
}
#define CP_COMMIT() asm volatile("cp.async.commit_group;" ::: "memory")
#define CP_WAIT(n)  asm volatile("cp.async.wait_group %0;" :: "n"(n) : "memory")

__device__ __forceinline__ void ldsm4(uint32_t (&r)[4], uint32_t addr) {
    asm volatile("ldmatrix.sync.aligned.m8n8.x4.shared.b16 {%0,%1,%2,%3}, [%4];"
                 : "=r"(r[0]), "=r"(r[1]), "=r"(r[2]), "=r"(r[3]) : "r"(addr));
}
__device__ __forceinline__ uint32_t f2tf32(float a) {
    uint32_t r;
    asm("cvt.rna.tf32.f32 %0, %1;" : "=r"(r) : "f"(a));
    return r;
}
__device__ __forceinline__ void tf32_split(float a, uint32_t& h, uint32_t& l) {
    h = f2tf32(a);
    l = f2tf32(a - __uint_as_float(h));
}
__device__ __forceinline__ void mma_tf32(float (&d)[4], const uint32_t (&a)[4],
                                         uint32_t b0, uint32_t b1) {
    asm volatile("mma.sync.aligned.m16n8k8.row.col.f32.tf32.tf32.f32 "
                 "{%0,%1,%2,%3}, {%4,%5,%6,%7}, {%8,%9}, {%0,%1,%2,%3};"
                 : "+f"(d[0]), "+f"(d[1]), "+f"(d[2]), "+f"(d[3])
                 : "r"(a[0]), "r"(a[1]), "r"(a[2]), "r"(a[3]), "r"(b0), "r"(b1));
}

// ---------------- K1: weight normalization -> split tf32 planes ------------
__global__ __launch_bounds__(256) void norm_k(const float* __restrict__ wqkv,
                                              const float* __restrict__ wproj) {
    int row = blockIdx.x;
    const float* src;
    uint32_t *dh, *dl;
    if (row < C3) { src = wqkv + row * CDIM; dh = g_wqh + row * CDIM; dl = g_wql + row * CDIM; }
    else { src = wproj + (row - C3) * CDIM; dh = g_wph + (row - C3) * CDIM; dl = g_wpl + (row - C3) * CDIM; }

    float ss = 0.f;
    for (int i = threadIdx.x; i < CDIM; i += 256) { float v = src[i]; ss = fmaf(v, v, ss); }
    #pragma unroll
    for (int off = 16; off; off >>= 1) ss += __shfl_xor_sync(0xffffffffu, ss, off);

    __shared__ float sred[8];
    __shared__ float sscale;
    if ((threadIdx.x & 31) == 0) sred[threadIdx.x >> 5] = ss;
    __syncthreads();
    if (threadIdx.x == 0) {
        float t = 0.f;
        #pragma unroll
        for (int i = 0; i < 8; i++) t += sred[i];
        sscale = 1.0f / (sqrtf(768.0f) * 1e-4f + sqrtf(t));
    }
    __syncthreads();
    float sc = sscale;
    for (int i = threadIdx.x; i < CDIM; i += 256) {
        uint32_t h, l;
        tf32_split(src[i] * sc, h, l);
        dh[i] = h; dl[i] = l;
    }
}

// ---------------- K2: elementwise x -> tf32 hi/lo planes -------------------
__global__ __launch_bounds__(256) void xsplit(const float* __restrict__ x) {
    int i = blockIdx.x * 256 + threadIdx.x;
    uint32_t h, l;
    tf32_split(x[i], h, l);
    g_xh[i] = h; g_xl[i] = l;
}

// ---------------- K3/K6: 3xTF32 HMMA GEMM, pre-split operands --------------
#define GA_ROW 144
#define GB_ROW 544
#define GA_PLANE 18432   // 128*144
#define GB_PLANE 17408   // 32*544
#define G_STAGE  71680   // 2*(GA_PLANE+GB_PLANE)
#define G_SMEM   143360

template <int EPI>
__global__ __launch_bounds__(256) void gemm_f3(const float* __restrict__ Xres,
                                               float* __restrict__ Out) {
    extern __shared__ char smem[];
    const uint32_t sb = smem_to_u32(smem);
    const int tid = threadIdx.x, wid = tid >> 5, lid = tid & 31;
    const int o0 = blockIdx.y * 128;
    const int n0 = blockIdx.x * 128;
    const int bt = n0 >> 8;
    const int pb = n0 & 255;

    const uint32_t* Awh = (EPI == 0 ? g_wqh : g_wph) + o0 * CDIM;
    const uint32_t* Awl = (EPI == 0 ? g_wql : g_wpl) + o0 * CDIM;
    const uint32_t* Bgh = (EPI == 0 ? g_xh : g_yh) + bt * XSTRIDE + pb;
    const uint32_t* Bgl = (EPI == 0 ? g_xl : g_yl) + bt * XSTRIDE + pb;

    float acc[2][8][4];
    #pragma unroll
    for (int mi = 0; mi < 2; mi++)
        #pragma unroll
        for (int ni = 0; ni < 8; ni++)
            #pragma unroll
            for (int d = 0; d < 4; d++) acc[mi][ni][d] = 0.f;

    const int wr = wid & 3, wc = wid >> 2;
    const int g = lid >> 2, tg = lid & 3;
    const int sel = lid >> 3, r8 = lid & 7;
    const uint32_t aoff = (uint32_t)(((sel & 1) * 8 + r8) * GA_ROW + (sel >> 1) * 16);

    auto copy_stage = [&](int st, int kc) {
        uint32_t s0 = sb + st * G_STAGE;
        #pragma unroll
        for (int i = 0; i < 4; i++) {
            int idx = tid + i * 256;
            int row = idx >> 3, u = idx & 7;
            uint32_t d = s0 + row * GA_ROW + u * 16;
            cp16(d,            Awh + row * CDIM + kc + u * 4);
            cp16(d + GA_PLANE, Awl + row * CDIM + kc + u * 4);
        }
        uint32_t sB0 = s0 + 2 * GA_PLANE;
        #pragma unroll
        for (int i = 0; i < 4; i++) {
            int idx = tid + i * 256;
            int r = idx >> 5, u = idx & 31;
            uint32_t d = sB0 + r * GB_ROW + u * 16;
            cp16(d,            Bgh + (kc + r) * 256 + u * 4);
            cp16(d + GB_PLANE, Bgl + (kc + r) * 256 + u * 4);
        }
        CP_COMMIT();
    };

    copy_stage(0, 0);
    int st = 0;
    for (int kc = 0; kc < CDIM; kc += 32, st ^= 1) {
        if (kc + 32 < CDIM) {
            copy_stage(st ^ 1, kc + 32);
            CP_WAIT(1);
        } else {
            CP_WAIT(0);
        }
        __syncthreads();

        const uint32_t sAh = sb + st * G_STAGE;
        const uint32_t sAl = sAh + GA_PLANE;
        const uint32_t sBh = sAh + 2 * GA_PLANE;
        const uint32_t sBl = sBh + GB_PLANE;
        #pragma unroll
        for (int ks = 0; ks < 4; ks++) {
            const int kk = ks * 8;
            uint32_t ah[2][4], al[2][4];
            #pragma unroll
            for (int mi = 0; mi < 2; mi++) {
                uint32_t rbase = (uint32_t)((wr * 32 + mi * 16) * GA_ROW) + aoff + ks * 32;
                ldsm4(ah[mi], sAh + rbase);
                ldsm4(al[mi], sAl + rbase);
            }
            const uint32_t rk0 = (kk + tg) * GB_ROW;
            const uint32_t rk1 = (kk + tg + 4) * GB_ROW;
            #pragma unroll
            for (int ni = 0; ni < 8; ni++) {
                const uint32_t n4 = (uint32_t)((wc * 64 + ni * 8 + g) * 4);
                uint32_t b0h = lds_u32(sBh + rk0 + n4);
                uint32_t b1h = lds_u32(sBh + rk1 + n4);
                uint32_t b0l = lds_u32(sBl + rk0 + n4);
                uint32_t b1l = lds_u32(sBl + rk1 + n4);
                mma_tf32(acc[0][ni], ah[0], b0h, b1h);
                mma_tf32(acc[1][ni], ah[1], b0h, b1h);
                mma_tf32(acc[0][ni], ah[0], b0l, b1l);
                mma_tf32(acc[1][ni], ah[1], b0l, b1l);
                mma_tf32(acc[0][ni], al[0], b0h, b1h);
                mma_tf32(acc[1][ni], al[1], b0h, b1h);
            }
        }
        __syncthreads();
    }

    const int cB = tg * 2;

    if (EPI == 0) {
        const int qi = blockIdx.y / 6;
        const int rem0 = o0 - qi * CDIM + wr * 32;
        const int bb = bt >> 3, ti = bt & 7;
        #pragma unroll
        for (int mi = 0; mi < 2; mi++)
            #pragma unroll
            for (int dd = 0; dd < 2; dd++) {
                int rem = rem0 + mi * 16 + g + dd * 8;
                int mh = rem >> 6, cc = rem & 63;
                if (qi < 2) {
                    float* dst = (qi == 0) ? g_q : g_k;
                    int rowbase = ((bb * NM + mh) * SLEN + ti * 256 + pb) * HD + cc;
                    #pragma unroll
                    for (int ni = 0; ni < 8; ni++) {
                        int p = wc * 64 + ni * 8 + cB;
                        dst[rowbase + p * HD]       = acc[mi][ni][dd * 2];
                        dst[rowbase + (p + 1) * HD] = acc[mi][ni][dd * 2 + 1];
                    }
                } else {
                    int vbase = ((bb * NM + mh) * HD + cc) * SLEN + ti * 256 + pb;
                    #pragma unroll
                    for (int ni = 0; ni < 8; ni++) {
                        int p = wc * 64 + ni * 8 + cB;
                        uint32_t h, l;
                        tf32_split(acc[mi][ni][dd * 2], h, l);
                        g_vh[vbase + p] = h; g_vl[vbase + p] = l;
                        tf32_split(acc[mi][ni][dd * 2 + 1], h, l);
                        g_vh[vbase + p + 1] = h; g_vl[vbase + p + 1] = l;
                    }
                }
            }
    } else {
        const float c1 = 0.9191450300180578f;   // 0.7 / sqrt(0.58)
        const float c2 = 0.3939192985791676f;   // 0.3 / sqrt(0.58)
        #pragma unroll
        for (int mi = 0; mi < 2; mi++)
            #pragma unroll
            for (int dd = 0; dd < 2; dd++) {
                int o = o0 + wr * 32 + mi * 16 + g + dd * 8;
                int ib = bt * XSTRIDE + o * 256 + pb + wc * 64 + cB;
                #pragma unroll
                for (int ni = 0; ni < 8; ni++) {
                    int idx = ib + ni * 8;
                    Out[idx]     = Xres[idx] * c1 + acc[mi][ni][dd * 2] * c2;
                    Out[idx + 1] = Xres[idx + 1] * c1 + acc[mi][ni][dd * 2 + 1] * c2;
                }
            }
    }
}

// ---------------- K4: RoPE over frame index; K -> tf32 split ----------------
__global__ __launch_bounds__(256) void rope_k() {
    int idx = blockIdx.x * 256 + threadIdx.x;
    int d2 = idx & 31;
    int s = (idx >> 5) & 2047;
    int bm = idx >> 16;
    int ti = s >> 8;
    float ang = (float)ti * __powf(10000.0f, -(float)d2 * (1.0f / 32.0f));
    float sn, cs;
    __sincosf(ang, &sn, &cs);
    int base = (bm * SLEN + s) * HD + d2;
    float q1 = g_q[base], q2 = g_q[base + 32];
    g_q[base]      = q1 * cs - q2 * sn;
    g_q[base + 32] = q1 * sn + q2 * cs;
    float k1 = g_k[base], k2 = g_k[base + 32];
    float kr1 = k1 * cs - k2 * sn;
    float kr2 = k1 * sn + k2 * cs;
    uint32_t h, l;
    tf32_split(kr1, h, l); g_kh[base] = h;      g_kl[base] = l;
    tf32_split(kr2, h, l); g_kh[base + 32] = h; g_kl[base + 32] = l;
}

// ---------------- K5: block-causal flash attention, 3xTF32 + ldmatrix ------
// Split accumulators: hi-term and correction-term MMAs target separate
// register sets (s/sc, o/oc) -> 2x independent tensor chains per warp.
#define KP_ROW 272
#define VP_ROW 144
#define K_PLANE 8704     // 32*272
#define V_PLANE 9216     // 64*144
#define FS_STAGE 35840   // 2*K_PLANE + 2*V_PLANE
#define FS_P 71680       // 2 stages
#define FS_TOTAL (FS_P + 4 * 4608)   // 90112

__global__ __launch_bounds__(128) void flash_tc() {
    extern __shared__ char fsm[];
    const uint32_t sb = smem_to_u32(fsm);
    const int tid = threadIdx.x, w = tid >> 5, lid = tid & 31;
    const int g = lid >> 2, tg = lid & 3;
    const int sel = lid >> 3, r8 = lid & 7;
    const int qt = 31 - blockIdx.x;      // heavy causal tiles first
    const int bm = blockIdx.y;
    const int s0 = qt * 64;
    const int fr = qt >> 2;
    const int nch = (fr + 1) * 8;        // 32-key chunks

    const uint32_t PSh = sb + FS_P + w * 4608;
    const uint32_t PSl = PSh + 2304;

    const float* Qg = g_q + (bm * SLEN + s0 + w * 16) * HD;
    const uint32_t* Khg = g_kh + bm * SLEN * HD;
    const uint32_t* Klg = g_kl + bm * SLEN * HD;
    const uint32_t* Vhg = g_vh + bm * HD * SLEN;   // [c][s]
    const uint32_t* Vlg = g_vl + bm * HD * SLEN;

    const uint32_t koff0 = (uint32_t)(((sel >> 1) * 8 + r8) * KP_ROW + (sel & 1) * 16);
    const uint32_t koff1 = koff0 + 16 * KP_ROW;
    const uint32_t voff0 = (uint32_t)(((sel >> 1) * 8 + r8) * VP_ROW + (sel & 1) * 16);
    const uint32_t poff  = (uint32_t)(((sel & 1) * 8 + r8) * VP_ROW + (sel >> 1) * 16);

    // register-resident Q fragments (split once)
    uint32_t qh[8][4], ql[8][4];
    #pragma unroll
    for (int ks = 0; ks < 8; ks++) {
        int c0 = ks * 8 + tg;
        tf32_split(Qg[g * 64 + c0],           qh[ks][0], ql[ks][0]);
        tf32_split(Qg[(g + 8) * 64 + c0],     qh[ks][1], ql[ks][1]);
        tf32_split(Qg[g * 64 + c0 + 4],       qh[ks][2], ql[ks][2]);
        tf32_split(Qg[(g + 8) * 64 + c0 + 4], qh[ks][3], ql[ks][3]);
    }

    float o[8][4], oc[8][4];
    #pragma unroll
    for (int ct = 0; ct < 8; ct++)
        #pragma unroll
        for (int d = 0; d < 4; d++) { o[ct][d] = 0.f; oc[ct][d] = 0.f; }
    float m0 = -1e30f, m1 = -1e30f, l0 = 0.f, l1 = 0.f;

    auto stage = [&](int st, int k0) {
        uint32_t b0 = sb + st * FS_STAGE;
        #pragma unroll
        for (int i = 0; i < 4; i++) {
            int idx = tid + i * 128;          // 0..511
            int key = idx >> 4, c4 = idx & 15;
            uint32_t dK = b0 + key * KP_ROW + c4 * 16;
            int goK = (k0 + key) * 64 + c4 * 4;
            cp16(dK,           Khg + goK);
            cp16(dK + K_PLANE, Klg + goK);
            int cc = idx >> 3, kg = idx & 7;
            uint32_t dV = b0 + 2 * K_PLANE + cc * VP_ROW + kg * 16;
            int goV = cc * SLEN + k0 + kg * 4;
            cp16(dV,           Vhg + goV);
            cp16(dV + V_PLANE, Vlg + goV);
        }
        CP_COMMIT();
    };

    stage(0, 0);
    int st = 0;
    for (int ic = 0; ic < nch; ic++, st ^= 1) {
        if (ic + 1 < nch) {
            stage(st ^ 1, (ic + 1) * 32);
            CP_WAIT(1);
        } else {
            CP_WAIT(0);
        }
        __syncthreads();
        const uint32_t bKh = sb + st * FS_STAGE;
        const uint32_t bKl = bKh + K_PLANE;
        const uint32_t bVh = bKh + 2 * K_PLANE;
        const uint32_t bVl = bVh + V_PLANE;

        // ---- S = Q K^T: hi-product -> s, corrections -> sc (independent chains)
        float s[4][4], scx[4][4];
        #pragma unroll
        for (int nt = 0; nt < 4; nt++)
            #pragma unroll
            for (int d = 0; d < 4; d++) { s[nt][d] = 0.f; scx[nt][d] = 0.f; }
        #pragma unroll
        for (int ks = 0; ks < 8; ks++) {
            const uint32_t kb = ks * 32;
            uint32_t kh0[4], kh1[4], kl0[4], kl1[4];
            ldsm4(kh0, bKh + koff0 + kb);
            ldsm4(kh1, bKh + koff1 + kb);
            ldsm4(kl0, bKl + koff0 + kb);
            ldsm4(kl1, bKl + koff1 + kb);
            mma_tf32(s[0],   qh[ks], kh0[0], kh0[1]);
            mma_tf32(s[1],   qh[ks], kh0[2], kh0[3]);
            mma_tf32(s[2],   qh[ks], kh1[0], kh1[1]);
            mma_tf32(s[3],   qh[ks], kh1[2], kh1[3]);
            mma_tf32(scx[0], qh[ks], kl0[0], kl0[1]);
            mma_tf32(scx[1], qh[ks], kl0[2], kl0[3]);
            mma_tf32(scx[2], qh[ks], kl1[0], kl1[1]);
            mma_tf32(scx[3], qh[ks], kl1[2], kl1[3]);
            mma_tf32(scx[0], ql[ks], kh0[0], kh0[1]);
            mma_tf32(scx[1], ql[ks], kh0[2], kh0[3]);
            mma_tf32(scx[2], ql[ks], kh1[0], kh1[1]);
            mma_tf32(scx[3], ql[ks], kh1[2], kh1[3]);
        }
        #pragma unroll
        for (int nt = 0; nt < 4; nt++)
            #pragma unroll
            for (int d = 0; d < 4; d++) s[nt][d] += scx[nt][d];

        // ---- online softmax (rows g and g+8; reduce over the 4 tg lanes) ----
        float mx0 = -1e30f, mx1 = -1e30f;
        #pragma unroll
        for (int nt = 0; nt < 4; nt++) {
            #pragma unroll
            for (int d = 0; d < 4; d++) s[nt][d] *= 0.125f;
            mx0 = fmaxf(mx0, fmaxf(s[nt][0], s[nt][1]));
            mx1 = fmaxf(mx1, fmaxf(s[nt][2], s[nt][3]));
        }
        mx0 = fmaxf(mx0, __shfl_xor_sync(0xffffffffu, mx0, 1));
        mx0 = fmaxf(mx0, __shfl_xor_sync(0xffffffffu, mx0, 2));
        mx1 = fmaxf(mx1, __shfl_xor_sync(0xffffffffu, mx1, 1));
        mx1 = fmaxf(mx1, __shfl_xor_sync(0xffffffffu, mx1, 2));
        float mn0 = fmaxf(m0, mx0), mn1 = fmaxf(m1, mx1);
        float cr0 = __expf(m0 - mn0), cr1 = __expf(m1 - mn1);
        m0 = mn0; m1 = mn1;
        float rs0 = 0.f, rs1 = 0.f;
        #pragma unroll
        for (int nt = 0; nt < 4; nt++) {
            s[nt][0] = __expf(s[nt][0] - mn0);
            s[nt][1] = __expf(s[nt][1] - mn0);
            s[nt][2] = __expf(s[nt][2] - mn1);
            s[nt][3] = __expf(s[nt][3] - mn1);
            rs0 += s[nt][0] + s[nt][1];
            rs1 += s[nt][2] + s[nt][3];
        }
        rs0 += __shfl_xor_sync(0xffffffffu, rs0, 1);
        rs0 += __shfl_xor_sync(0xffffffffu, rs0, 2);
        rs1 += __shfl_xor_sync(0xffffffffu, rs1, 1);
        rs1 += __shfl_xor_sync(0xffffffffu, rs1, 2);
        l0 = l0 * cr0 + rs0;
        l1 = l1 * cr1 + rs1;
        #pragma unroll
        for (int ct = 0; ct < 8; ct++) {
            o[ct][0] *= cr0;  o[ct][1] *= cr0;
            o[ct][2] *= cr1;  o[ct][3] *= cr1;
            oc[ct][0] *= cr0; oc[ct][1] *= cr0;
            oc[ct][2] *= cr1; oc[ct][3] *= cr1;
        }

        // ---- stage P pre-split into Ph/Pl planes ----
        #pragma unroll
        for (int nt = 0; nt < 4; nt++) {
            uint32_t h0, h1, h2, h3, lo0, lo1, lo2, lo3;
            tf32_split(s[nt][0], h0, lo0);
            tf32_split(s[nt][1], h1, lo1);
            tf32_split(s[nt][2], h2, lo2);
            tf32_split(s[nt][3], h3, lo3);
            uint32_t cofs = (uint32_t)((nt * 8 + 2 * tg) * 4);
            sts64(PSh + g * VP_ROW + cofs,       h0, h1);
            sts64(PSh + (g + 8) * VP_ROW + cofs, h2, h3);
            sts64(PSl + g * VP_ROW + cofs,       lo0, lo1);
            sts64(PSl + (g + 8) * VP_ROW + cofs, lo2, lo3);
        }
        __syncwarp();

        // ---- O += P V: hi-product -> o, corrections -> oc ----
        #pragma unroll
        for (int k2 = 0; k2 < 4; k2++) {
            const uint32_t kb2 = k2 * 32;
            uint32_t ph[4], pl[4];
            ldsm4(ph, PSh + poff + kb2);
            ldsm4(pl, PSl + poff + kb2);
            #pragma unroll
            for (int j = 0; j < 4; j++) {
                uint32_t vh4[4], vl4[4];
                uint32_t vo = voff0 + (uint32_t)(j * 16 * VP_ROW) + kb2;
                ldsm4(vh4, bVh + vo);
                ldsm4(vl4, bVl + vo);
                mma_tf32(o[2 * j],      ph, vh4[0], vh4[1]);
                mma_tf32(o[2 * j + 1],  ph, vh4[2], vh4[3]);
                mma_tf32(oc[2 * j],     ph, vl4[0], vl4[1]);
                mma_tf32(oc[2 * j + 1], ph, vl4[2], vl4[3]);
                mma_tf32(oc[2 * j],     pl, vh4[0], vh4[1]);
                mma_tf32(oc[2 * j + 1], pl, vh4[2], vh4[3]);
            }
        }
        __syncthreads();
    }

    // ---- epilogue: O = (o + oc)/l, split, transpose via smem, write yh/yl ----
    const uint32_t TH = sb, TL = sb + 17408;
    float li0 = 1.f / l0, li1 = 1.f / l1;
    #pragma unroll
    for (int ct = 0; ct < 8; ct++) {
        int c0 = ct * 8 + 2 * tg;
        int row0 = w * 16 + g, row1 = row0 + 8;
        uint32_t h, l;
        tf32_split((o[ct][0] + oc[ct][0]) * li0, h, l);
        sts_u32(TH + c0 * 272 + row0 * 4, h); sts_u32(TL + c0 * 272 + row0 * 4, l);
        tf32_split((o[ct][1] + oc[ct][1]) * li0, h, l);
        sts_u32(TH + (c0 + 1) * 272 + row0 * 4, h); sts_u32(TL + (c0 + 1) * 272 + row0 * 4, l);
        tf32_split((o[ct][2] + oc[ct][2]) * li1, h, l);
        sts_u32(TH + c0 * 272 + row1 * 4, h); sts_u32(TL + c0 * 272 + row1 * 4, l);
        tf32_split((o[ct][3] + oc[ct][3]) * li1, h, l);
        sts_u32(TH + (c0 + 1) * 272 + row1 * 4, h); sts_u32(TL + (c0 + 1) * 272 + row1 * 4, l);
    }
    __syncthreads();
    const int bb = bm / NM, mh = bm - bb * NM;
    const int bt = bb * NT + fr;
    const int p0 = (qt & 3) * 64;
    const int obase = bt * XSTRIDE + mh * 256 + p0;
    #pragma unroll
    for (int it = 0; it < 32; it++) {
        int idx = tid + it * 128;       // 0..4095
        int c = idx >> 6, rr = idx & 63;
        g_yh[obase + c * 3072 + rr] = lds_u32(TH + c * 272 + rr * 4);
        g_yl[obase + c * 3072 + rr] = lds_u32(TL + c * 272 + rr * 4);
    }
}

// ---------------- launch ----------------
extern "C" void kernel_launch(void* const* d_in, const int* in_sizes, int n_in,
                              void* d_out, int out_size) {
    const float* x = (const float*)d_in[0];
    const float* wqkv = (const float*)d_in[1];
    const float* wproj = (const float*)d_in[2];
    float* out = (float*)d_out;

    cudaFuncSetAttribute(gemm_f3<0>, cudaFuncAttributeMaxDynamicSharedMemorySize, G_SMEM);
    cudaFuncSetAttribute(gemm_f3<1>, cudaFuncAttributeMaxDynamicSharedMemorySize, G_SMEM);
    cudaFuncSetAttribute(flash_tc, cudaFuncAttributeMaxDynamicSharedMemorySize, FS_TOTAL);

    norm_k<<<C3 + CDIM, 256>>>(wqkv, wproj);
    xsplit<<<(BT * CDIM * 256) / 256, 256>>>(x);
    gemm_f3<0><<<dim3(32, 18), 256, G_SMEM>>>(nullptr, nullptr);
    rope_k<<<(NB * NM * SLEN * 32) / 256, 256>>>();
    flash_tc<<<dim3(32, 24), 128, FS_TOTAL>>>();
    gemm_f3<1><<<dim3(32, 6), 256, G_SMEM>>>(x, out);
}

// round 12
// speedup vs baseline: 1.0208x; 1.0208x over previous
#include <cuda_runtime.h>
#include <cuda_bf16.h>
#include <math.h>
#include <cstdint>

// ---------------------------------------------------------------------------
// VideoAttention: b=2, t=8, C=768, h=w=16 -> hw=256, S=2048, heads=12, c=64
//   K1 norm_k    : EDM2 MP weight norm -> pre-split tf32 hi/lo weight planes
//   K2 xsplit    : x -> tf32 hi/lo planes
//   K3 gemm_f3<0>: 3xTF32 HMMA GEMM -> q,k fp32; V pre-split + transposed [bm][c][s]
//   K4 rope_k    : rotary over frame index; k -> tf32 hi/lo split
//   K5 flash_tc  : block-causal flash attention, 3xTF32 HMMA, 64-KEY CHUNKS
//                  (halves softmax passes/barriers - the measured serial binder)
//   K6 gemm_f3<1>: 3xTF32 HMMA proj GEMM + mp_sum residual -> out
// ---------------------------------------------------------------------------

#define NB   2
#define NT   8
#define NM   12
#define HD   64
#define C3   2304
#define CDIM 768
#define SLEN 2048
#define BT   16
#define XSTRIDE 196608   // 768*256

__device__ float g_q[NB * NM * SLEN * HD];
__device__ float g_k[NB * NM * SLEN * HD];
__device__ uint32_t g_kh[NB * NM * SLEN * HD], g_kl[NB * NM * SLEN * HD];
__device__ uint32_t g_vh[NB * NM * SLEN * HD], g_vl[NB * NM * SLEN * HD]; // [bm][c][s]
__device__ uint32_t g_wqh[C3 * CDIM],  g_wql[C3 * CDIM];
__device__ uint32_t g_wph[CDIM * CDIM], g_wpl[CDIM * CDIM];
__device__ uint32_t g_xh[BT * CDIM * 256], g_xl[BT * CDIM * 256];
__device__ uint32_t g_yh[BT * CDIM * 256], g_yl[BT * CDIM * 256];

// ======================= PTX helpers ===================
__device__ __forceinline__ uint32_t smem_to_u32(const void* p) {
    uint32_t a;
    asm("{ .reg .u64 t; cvta.to.shared.u64 t, %1; cvt.u32.u64 %0, t; }" : "=r"(a) : "l"(p));
    return a;
}
__device__ __forceinline__ uint32_t lds_u32(uint32_t addr) {
    uint32_t v;
    asm volatile("ld.shared.b32 %0, [%1];" : "=r"(v) : "r"(addr));
    return v;
}
__device__ __forceinline__ void sts_u32(uint32_t addr, uint32_t v) {
    asm volatile("st.shared.b32 [%0], %1;" :: "r"(addr), "r"(v));
}
__device__ __forceinline__ void sts64(uint32_t addr, uint32_t a, uint32_t b) {
    asm volatile("st.shared.v2.b32 [%0], {%1,%2};" :: "r"(addr), "r"(a), "r"(b));
}
__device__ __forceinline__ void cp16(uint32_t dst, const void* src) {
    asm volatile("cp.async.cg.shared.global [%0], [%1], 16;" :: "r"(dst), "l"(src));
}
#define CP_COMMIT() asm volatile("cp.async.commit_group;" ::: "memory")
#define CP_WAIT(n)  asm volatile("cp.async.wait_group %0;" :: "n"(n) : "memory")

__device__ __forceinline__ void ldsm4(uint32_t (&r)[4], uint32_t addr) {
    asm volatile("ldmatrix.sync.aligned.m8n8.x4.shared.b16 {%0,%1,%2,%3}, [%4];"
                 : "=r"(r[0]), "=r"(r[1]), "=r"(r[2]), "=r"(r[3]) : "r"(addr));
}
__device__ __forceinline__ uint32_t f2tf32(float a) {
    uint32_t r;
    asm("cvt.rna.tf32.f32 %0, %1;" : "=r"(r) : "f"(a));
    return r;
}
__device__ __forceinline__ void tf32_split(float a, uint32_t& h, uint32_t& l) {
    h = f2tf32(a);
    l = f2tf32(a - __uint_as_float(h));
}
__device__ __forceinline__ void mma_tf32(float (&d)[4], const uint32_t (&a)[4],
                                         uint32_t b0, uint32_t b1) {
    asm volatile("mma.sync.aligned.m16n8k8.row.col.f32.tf32.tf32.f32 "
                 "{%0,%1,%2,%3}, {%4,%5,%6,%7}, {%8,%9}, {%0,%1,%2,%3};"
                 : "+f"(d[0]), "+f"(d[1]), "+f"(d[2]), "+f"(d[3])
                 : "r"(a[0]), "r"(a[1]), "r"(a[2]), "r"(a[3]), "r"(b0), "r"(b1));
}

// ---------------- K1: weight normalization -> split tf32 planes ------------
__global__ __launch_bounds__(256) void norm_k(const float* __restrict__ wqkv,
                                              const float* __restrict__ wproj) {
    int row = blockIdx.x;
    const float* src;
    uint32_t *dh, *dl;
    if (row < C3) { src = wqkv + row * CDIM; dh = g_wqh + row * CDIM; dl = g_wql + row * CDIM; }
    else { src = wproj + (row - C3) * CDIM; dh = g_wph + (row - C3) * CDIM; dl = g_wpl + (row - C3) * CDIM; }

    float ss = 0.f;
    for (int i = threadIdx.x; i < CDIM; i += 256) { float v = src[i]; ss = fmaf(v, v, ss); }
    #pragma unroll
    for (int off = 16; off; off >>= 1) ss += __shfl_xor_sync(0xffffffffu, ss, off);

    __shared__ float sred[8];
    __shared__ float sscale;
    if ((threadIdx.x & 31) == 0) sred[threadIdx.x >> 5] = ss;
    __syncthreads();
    if (threadIdx.x == 0) {
        float t = 0.f;
        #pragma unroll
        for (int i = 0; i < 8; i++) t += sred[i];
        sscale = 1.0f / (sqrtf(768.0f) * 1e-4f + sqrtf(t));
    }
    __syncthreads();
    float sc = sscale;
    for (int i = threadIdx.x; i < CDIM; i += 256) {
        uint32_t h, l;
        tf32_split(src[i] * sc, h, l);
        dh[i] = h; dl[i] = l;
    }
}

// ---------------- K2: elementwise x -> tf32 hi/lo planes -------------------
__global__ __launch_bounds__(256) void xsplit(const float* __restrict__ x) {
    int i = blockIdx.x * 256 + threadIdx.x;
    uint32_t h, l;
    tf32_split(x[i], h, l);
    g_xh[i] = h; g_xl[i] = l;
}

// ---------------- K3/K6: 3xTF32 HMMA GEMM, pre-split operands --------------
#define GA_ROW 144
#define GB_ROW 544
#define GA_PLANE 18432   // 128*144
#define GB_PLANE 17408   // 32*544
#define G_STAGE  71680   // 2*(GA_PLANE+GB_PLANE)
#define G_SMEM   143360

template <int EPI>
__global__ __launch_bounds__(256) void gemm_f3(const float* __restrict__ Xres,
                                               float* __restrict__ Out) {
    extern __shared__ char smem[];
    const uint32_t sb = smem_to_u32(smem);
    const int tid = threadIdx.x, wid = tid >> 5, lid = tid & 31;
    const int o0 = blockIdx.y * 128;
    const int n0 = blockIdx.x * 128;
    const int bt = n0 >> 8;
    const int pb = n0 & 255;

    const uint32_t* Awh = (EPI == 0 ? g_wqh : g_wph) + o0 * CDIM;
    const uint32_t* Awl = (EPI == 0 ? g_wql : g_wpl) + o0 * CDIM;
    const uint32_t* Bgh = (EPI == 0 ? g_xh : g_yh) + bt * XSTRIDE + pb;
    const uint32_t* Bgl = (EPI == 0 ? g_xl : g_yl) + bt * XSTRIDE + pb;

    float acc[2][8][4];
    #pragma unroll
    for (int mi = 0; mi < 2; mi++)
        #pragma unroll
        for (int ni = 0; ni < 8; ni++)
            #pragma unroll
            for (int d = 0; d < 4; d++) acc[mi][ni][d] = 0.f;

    const int wr = wid & 3, wc = wid >> 2;
    const int g = lid >> 2, tg = lid & 3;
    const int sel = lid >> 3, r8 = lid & 7;
    const uint32_t aoff = (uint32_t)(((sel & 1) * 8 + r8) * GA_ROW + (sel >> 1) * 16);

    auto copy_stage = [&](int st, int kc) {
        uint32_t s0 = sb + st * G_STAGE;
        #pragma unroll
        for (int i = 0; i < 4; i++) {
            int idx = tid + i * 256;
            int row = idx >> 3, u = idx & 7;
            uint32_t d = s0 + row * GA_ROW + u * 16;
            cp16(d,            Awh + row * CDIM + kc + u * 4);
            cp16(d + GA_PLANE, Awl + row * CDIM + kc + u * 4);
        }
        uint32_t sB0 = s0 + 2 * GA_PLANE;
        #pragma unroll
        for (int i = 0; i < 4; i++) {
            int idx = tid + i * 256;
            int r = idx >> 5, u = idx & 31;
            uint32_t d = sB0 + r * GB_ROW + u * 16;
            cp16(d,            Bgh + (kc + r) * 256 + u * 4);
            cp16(d + GB_PLANE, Bgl + (kc + r) * 256 + u * 4);
        }
        CP_COMMIT();
    };

    copy_stage(0, 0);
    int st = 0;
    for (int kc = 0; kc < CDIM; kc += 32, st ^= 1) {
        if (kc + 32 < CDIM) {
            copy_stage(st ^ 1, kc + 32);
            CP_WAIT(1);
        } else {
            CP_WAIT(0);
        }
        __syncthreads();

        const uint32_t sAh = sb + st * G_STAGE;
        const uint32_t sAl = sAh + GA_PLANE;
        const uint32_t sBh = sAh + 2 * GA_PLANE;
        const uint32_t sBl = sBh + GB_PLANE;
        #pragma unroll
        for (int ks = 0; ks < 4; ks++) {
            const int kk = ks * 8;
            uint32_t ah[2][4], al[2][4];
            #pragma unroll
            for (int mi = 0; mi < 2; mi++) {
                uint32_t rbase = (uint32_t)((wr * 32 + mi * 16) * GA_ROW) + aoff + ks * 32;
                ldsm4(ah[mi], sAh + rbase);
                ldsm4(al[mi], sAl + rbase);
            }
            const uint32_t rk0 = (kk + tg) * GB_ROW;
            const uint32_t rk1 = (kk + tg + 4) * GB_ROW;
            #pragma unroll
            for (int ni = 0; ni < 8; ni++) {
                const uint32_t n4 = (uint32_t)((wc * 64 + ni * 8 + g) * 4);
                uint32_t b0h = lds_u32(sBh + rk0 + n4);
                uint32_t b1h = lds_u32(sBh + rk1 + n4);
                uint32_t b0l = lds_u32(sBl + rk0 + n4);
                uint32_t b1l = lds_u32(sBl + rk1 + n4);
                mma_tf32(acc[0][ni], ah[0], b0h, b1h);
                mma_tf32(acc[1][ni], ah[1], b0h, b1h);
                mma_tf32(acc[0][ni], ah[0], b0l, b1l);
                mma_tf32(acc[1][ni], ah[1], b0l, b1l);
                mma_tf32(acc[0][ni], al[0], b0h, b1h);
                mma_tf32(acc[1][ni], al[1], b0h, b1h);
            }
        }
        __syncthreads();
    }

    const int cB = tg * 2;

    if (EPI == 0) {
        const int qi = blockIdx.y / 6;
        const int rem0 = o0 - qi * CDIM + wr * 32;
        const int bb = bt >> 3, ti = bt & 7;
        #pragma unroll
        for (int mi = 0; mi < 2; mi++)
            #pragma unroll
            for (int dd = 0; dd < 2; dd++) {
                int rem = rem0 + mi * 16 + g + dd * 8;
                int mh = rem >> 6, cc = rem & 63;
                if (qi < 2) {
                    float* dst = (qi == 0) ? g_q : g_k;
                    int rowbase = ((bb * NM + mh) * SLEN + ti * 256 + pb) * HD + cc;
                    #pragma unroll
                    for (int ni = 0; ni < 8; ni++) {
                        int p = wc * 64 + ni * 8 + cB;
                        dst[rowbase + p * HD]       = acc[mi][ni][dd * 2];
                        dst[rowbase + (p + 1) * HD] = acc[mi][ni][dd * 2 + 1];
                    }
                } else {
                    int vbase = ((bb * NM + mh) * HD + cc) * SLEN + ti * 256 + pb;
                    #pragma unroll
                    for (int ni = 0; ni < 8; ni++) {
                        int p = wc * 64 + ni * 8 + cB;
                        uint32_t h, l;
                        tf32_split(acc[mi][ni][dd * 2], h, l);
                        g_vh[vbase + p] = h; g_vl[vbase + p] = l;
                        tf32_split(acc[mi][ni][dd * 2 + 1], h, l);
                        g_vh[vbase + p + 1] = h; g_vl[vbase + p + 1] = l;
                    }
                }
            }
    } else {
        const float c1 = 0.9191450300180578f;   // 0.7 / sqrt(0.58)
        const float c2 = 0.3939192985791676f;   // 0.3 / sqrt(0.58)
        #pragma unroll
        for (int mi = 0; mi < 2; mi++)
            #pragma unroll
            for (int dd = 0; dd < 2; dd++) {
                int o = o0 + wr * 32 + mi * 16 + g + dd * 8;
                int ib = bt * XSTRIDE + o * 256 + pb + wc * 64 + cB;
                #pragma unroll
                for (int ni = 0; ni < 8; ni++) {
                    int idx = ib + ni * 8;
                    Out[idx]     = Xres[idx] * c1 + acc[mi][ni][dd * 2] * c2;
                    Out[idx + 1] = Xres[idx + 1] * c1 + acc[mi][ni][dd * 2 + 1] * c2;
                }
            }
    }
}

// ---------------- K4: RoPE over frame index; K -> tf32 split ----------------
__global__ __launch_bounds__(256) void rope_k() {
    int idx = blockIdx.x * 256 + threadIdx.x;
    int d2 = idx & 31;
    int s = (idx >> 5) & 2047;
    int bm = idx >> 16;
    int ti = s >> 8;
    float ang = (float)ti * __powf(10000.0f, -(float)d2 * (1.0f / 32.0f));
    float sn, cs;
    __sincosf(ang, &sn, &cs);
    int base = (bm * SLEN + s) * HD + d2;
    float q1 = g_q[base], q2 = g_q[base + 32];
    g_q[base]      = q1 * cs - q2 * sn;
    g_q[base + 32] = q1 * sn + q2 * cs;
    float k1 = g_k[base], k2 = g_k[base + 32];
    float kr1 = k1 * cs - k2 * sn;
    float kr2 = k1 * sn + k2 * cs;
    uint32_t h, l;
    tf32_split(kr1, h, l); g_kh[base] = h;      g_kl[base] = l;
    tf32_split(kr2, h, l); g_kh[base + 32] = h; g_kl[base + 32] = l;
}

// ---------------- K5: block-causal flash attention, 64-key chunks ----------
// grid (16 q-tiles of 128 rows heavy-first, 24 bm), 256 threads / 8 warps;
// warp w owns q rows w*16..+16. 64-key chunks double-buffered (halved softmax
// passes + barriers vs 32-key chunks). smem 208896 B -> 1 CTA/SM.
#define KP_ROW 272
#define K_PLANE 17408    // 64*272
#define V_PLANE 17408    // 64 channels x 272
#define FS_STAGE 69632   // 2*K_PLANE + 2*V_PLANE
#define FS_P 139264      // 2 stages
#define FS_TOTAL (FS_P + 8 * 8704)   // 208896

__global__ __launch_bounds__(256) void flash_tc() {
    extern __shared__ char fsm[];
    const uint32_t sb = smem_to_u32(fsm);
    const int tid = threadIdx.x, w = tid >> 5, lid = tid & 31;
    const int g = lid >> 2, tg = lid & 3;
    const int sel = lid >> 3, r8 = lid & 7;
    const int qt = 15 - blockIdx.x;      // heavy causal tiles first
    const int bm = blockIdx.y;
    const int s0 = qt * 128;
    const int fr = qt >> 1;
    const int nch = (fr + 1) * 4;        // 64-key chunks

    const uint32_t PSh = sb + FS_P + w * 8704;
    const uint32_t PSl = PSh + 4352;

    const float* Qg = g_q + (bm * SLEN + s0 + w * 16) * HD;
    const uint32_t* Khg = g_kh + bm * SLEN * HD;
    const uint32_t* Klg = g_kl + bm * SLEN * HD;
    const uint32_t* Vhg = g_vh + bm * HD * SLEN;   // [c][s]
    const uint32_t* Vlg = g_vl + bm * HD * SLEN;

    const uint32_t koff0 = (uint32_t)(((sel >> 1) * 8 + r8) * KP_ROW + (sel & 1) * 16);
    const uint32_t koff1 = koff0 + 16 * KP_ROW;
    const uint32_t voff0 = (uint32_t)(((sel >> 1) * 8 + r8) * KP_ROW + (sel & 1) * 16);
    const uint32_t poff  = (uint32_t)(((sel & 1) * 8 + r8) * KP_ROW + (sel >> 1) * 16);

    // register-resident Q fragments (split once)
    uint32_t qh[8][4], ql[8][4];
    #pragma unroll
    for (int ks = 0; ks < 8; ks++) {
        int c0 = ks * 8 + tg;
        tf32_split(Qg[g * 64 + c0],           qh[ks][0], ql[ks][0]);
        tf32_split(Qg[(g + 8) * 64 + c0],     qh[ks][1], ql[ks][1]);
        tf32_split(Qg[g * 64 + c0 + 4],       qh[ks][2], ql[ks][2]);
        tf32_split(Qg[(g + 8) * 64 + c0 + 4], qh[ks][3], ql[ks][3]);
    }

    float o[8][4];
    #pragma unroll
    for (int ct = 0; ct < 8; ct++)
        #pragma unroll
        for (int d = 0; d < 4; d++) o[ct][d] = 0.f;
    float m0 = -1e30f, m1 = -1e30f, l0 = 0.f, l1 = 0.f;

    auto stage = [&](int st, int k0) {
        uint32_t b0 = sb + st * FS_STAGE;
        #pragma unroll
        for (int i = 0; i < 4; i++) {
            int idx = tid + i * 256;          // 0..1023
            int key = idx >> 4, c4 = idx & 15;
            uint32_t dK = b0 + key * KP_ROW + c4 * 16;
            int goK = (k0 + key) * 64 + c4 * 4;
            cp16(dK,           Khg + goK);
            cp16(dK + K_PLANE, Klg + goK);
            uint32_t dV = b0 + 2 * K_PLANE + key * KP_ROW + c4 * 16;   // key -> channel
            int goV = key * SLEN + k0 + c4 * 4;
            cp16(dV,           Vhg + goV);
            cp16(dV + V_PLANE, Vlg + goV);
        }
        CP_COMMIT();
    };

    stage(0, 0);
    int st = 0;
    for (int ic = 0; ic < nch; ic++, st ^= 1) {
        if (ic + 1 < nch) {
            stage(st ^ 1, (ic + 1) * 64);
            CP_WAIT(1);
        } else {
            CP_WAIT(0);
        }
        __syncthreads();
        const uint32_t bKh = sb + st * FS_STAGE;
        const uint32_t bKl = bKh + K_PLANE;
        const uint32_t bVh = bKh + 2 * K_PLANE;
        const uint32_t bVl = bVh + V_PLANE;

        // ---- S = Q K^T (16 rows x 64 keys per warp) ----
        float s[8][4];
        #pragma unroll
        for (int nt = 0; nt < 8; nt++)
            #pragma unroll
            for (int d = 0; d < 4; d++) s[nt][d] = 0.f;
        #pragma unroll
        for (int ks = 0; ks < 8; ks++) {
            const uint32_t kb = ks * 32;
            #pragma unroll
            for (int hh = 0; hh < 2; hh++) {
                const uint32_t kro = hh * (32 * KP_ROW);
                uint32_t kh0[4], kh1[4], kl0[4], kl1[4];
                ldsm4(kh0, bKh + kro + koff0 + kb);
                ldsm4(kh1, bKh + kro + koff1 + kb);
                ldsm4(kl0, bKl + kro + koff0 + kb);
                ldsm4(kl1, bKl + kro + koff1 + kb);
                mma_tf32(s[4 * hh + 0], qh[ks], kh0[0], kh0[1]);
                mma_tf32(s[4 * hh + 1], qh[ks], kh0[2], kh0[3]);
                mma_tf32(s[4 * hh + 2], qh[ks], kh1[0], kh1[1]);
                mma_tf32(s[4 * hh + 3], qh[ks], kh1[2], kh1[3]);
                mma_tf32(s[4 * hh + 0], qh[ks], kl0[0], kl0[1]);
                mma_tf32(s[4 * hh + 1], qh[ks], kl0[2], kl0[3]);
                mma_tf32(s[4 * hh + 2], qh[ks], kl1[0], kl1[1]);
                mma_tf32(s[4 * hh + 3], qh[ks], kl1[2], kl1[3]);
                mma_tf32(s[4 * hh + 0], ql[ks], kh0[0], kh0[1]);
                mma_tf32(s[4 * hh + 1], ql[ks], kh0[2], kh0[3]);
                mma_tf32(s[4 * hh + 2], ql[ks], kh1[0], kh1[1]);
                mma_tf32(s[4 * hh + 3], ql[ks], kh1[2], kh1[3]);
            }
        }

        // ---- online softmax (rows g and g+8; reduce over the 4 tg lanes) ----
        float mx0 = -1e30f, mx1 = -1e30f;
        #pragma unroll
        for (int nt = 0; nt < 8; nt++) {
            #pragma unroll
            for (int d = 0; d < 4; d++) s[nt][d] *= 0.125f;
            mx0 = fmaxf(mx0, fmaxf(s[nt][0], s[nt][1]));
            mx1 = fmaxf(mx1, fmaxf(s[nt][2], s[nt][3]));
        }
        mx0 = fmaxf(mx0, __shfl_xor_sync(0xffffffffu, mx0, 1));
        mx0 = fmaxf(mx0, __shfl_xor_sync(0xffffffffu, mx0, 2));
        mx1 = fmaxf(mx1, __shfl_xor_sync(0xffffffffu, mx1, 1));
        mx1 = fmaxf(mx1, __shfl_xor_sync(0xffffffffu, mx1, 2));
        float mn0 = fmaxf(m0, mx0), mn1 = fmaxf(m1, mx1);
        float cr0 = __expf(m0 - mn0), cr1 = __expf(m1 - mn1);
        m0 = mn0; m1 = mn1;
        float rs0 = 0.f, rs1 = 0.f;
        #pragma unroll
        for (int nt = 0; nt < 8; nt++) {
            s[nt][0] = __expf(s[nt][0] - mn0);
            s[nt][1] = __expf(s[nt][1] - mn0);
            s[nt][2] = __expf(s[nt][2] - mn1);
            s[nt][3] = __expf(s[nt][3] - mn1);
            rs0 += s[nt][0] + s[nt][1];
            rs1 += s[nt][2] + s[nt][3];
        }
        rs0 += __shfl_xor_sync(0xffffffffu, rs0, 1);
        rs0 += __shfl_xor_sync(0xffffffffu, rs0, 2);
        rs1 += __shfl_xor_sync(0xffffffffu, rs1, 1);
        rs1 += __shfl_xor_sync(0xffffffffu, rs1, 2);
        l0 = l0 * cr0 + rs0;
        l1 = l1 * cr1 + rs1;
        #pragma unroll
        for (int ct = 0; ct < 8; ct++) {
            o[ct][0] *= cr0; o[ct][1] *= cr0;
            o[ct][2] *= cr1; o[ct][3] *= cr1;
        }

        // ---- stage P pre-split into Ph/Pl planes (16 x 64) ----
        #pragma unroll
        for (int nt = 0; nt < 8; nt++) {
            uint32_t h0, h1, h2, h3, lo0, lo1, lo2, lo3;
            tf32_split(s[nt][0], h0, lo0);
            tf32_split(s[nt][1], h1, lo1);
            tf32_split(s[nt][2], h2, lo2);
            tf32_split(s[nt][3], h3, lo3);
            uint32_t cofs = (uint32_t)((nt * 8 + 2 * tg) * 4);
            sts64(PSh + g * KP_ROW + cofs,       h0, h1);
            sts64(PSh + (g + 8) * KP_ROW + cofs, h2, h3);
            sts64(PSl + g * KP_ROW + cofs,       lo0, lo1);
            sts64(PSl + (g + 8) * KP_ROW + cofs, lo2, lo3);
        }
        __syncwarp();

        // ---- O += P V (ldmatrix for P and V; k-dim = 64 keys) ----
        #pragma unroll
        for (int k2 = 0; k2 < 8; k2++) {
            const uint32_t kb2 = k2 * 32;
            uint32_t ph[4], pl[4];
            ldsm4(ph, PSh + poff + kb2);
            ldsm4(pl, PSl + poff + kb2);
            #pragma unroll
            for (int j = 0; j < 4; j++) {
                uint32_t vh4[4], vl4[4];
                uint32_t vo = voff0 + (uint32_t)(j * 16 * KP_ROW) + kb2;
                ldsm4(vh4, bVh + vo);
                ldsm4(vl4, bVl + vo);
                mma_tf32(o[2 * j],     ph, vh4[0], vh4[1]);
                mma_tf32(o[2 * j + 1], ph, vh4[2], vh4[3]);
                mma_tf32(o[2 * j],     ph, vl4[0], vl4[1]);
                mma_tf32(o[2 * j + 1], ph, vl4[2], vl4[3]);
                mma_tf32(o[2 * j],     pl, vh4[0], vh4[1]);
                mma_tf32(o[2 * j + 1], pl, vh4[2], vh4[3]);
            }
        }
        __syncthreads();
    }

    // ---- epilogue: O /= l, split, transpose via smem, write yh/yl ----
    const uint32_t TH = sb, TL = sb + 33792;   // 64 ch x 528B each
    float li0 = 1.f / l0, li1 = 1.f / l1;
    #pragma unroll
    for (int ct = 0; ct < 8; ct++) {
        int c0 = ct * 8 + 2 * tg;
        int row0 = w * 16 + g, row1 = row0 + 8;
        uint32_t h, l;
        tf32_split(o[ct][0] * li0, h, l);
        sts_u32(TH + c0 * 528 + row0 * 4, h); sts_u32(TL + c0 * 528 + row0 * 4, l);
        tf32_split(o[ct][1] * li0, h, l);
        sts_u32(TH + (c0 + 1) * 528 + row0 * 4, h); sts_u32(TL + (c0 + 1) * 528 + row0 * 4, l);
        tf32_split(o[ct][2] * li1, h, l);
        sts_u32(TH + c0 * 528 + row1 * 4, h); sts_u32(TL + c0 * 528 + row1 * 4, l);
        tf32_split(o[ct][3] * li1, h, l);
        sts_u32(TH + (c0 + 1) * 528 + row1 * 4, h); sts_u32(TL + (c0 + 1) * 528 + row1 * 4, l);
    }
    __syncthreads();
    const int bb = bm / NM, mh = bm - bb * NM;
    const int bt = bb * NT + fr;
    const int p0 = (qt & 1) * 128;
    const int obase = bt * XSTRIDE + mh * 256 + p0;
    #pragma unroll
    for (int it = 0; it < 32; it++) {
        int idx = tid + it * 256;       // 0..8191
        int c = idx >> 7, rr = idx & 127;
        g_yh[obase + c * 3072 + rr] = lds_u32(TH + c * 528 + rr * 4);
        g_yl[obase + c * 3072 + rr] = lds_u32(TL + c * 528 + rr * 4);
    }
}

// ---------------- launch ----------------
extern "C" void kernel_launch(void* const* d_in, const int* in_sizes, int n_in,
                              void* d_out, int out_size) {
    const float* x = (const float*)d_in[0];
    const float* wqkv = (const float*)d_in[1];
    const float* wproj = (const float*)d_in[2];
    float* out = (float*)d_out;

    cudaFuncSetAttribute(gemm_f3<0>, cudaFuncAttributeMaxDynamicSharedMemorySize, G_SMEM);
    cudaFuncSetAttribute(gemm_f3<1>, cudaFuncAttributeMaxDynamicSharedMemorySize, G_SMEM);
    cudaFuncSetAttribute(flash_tc, cudaFuncAttributeMaxDynamicSharedMemorySize, FS_TOTAL);

    norm_k<<<C3 + CDIM, 256>>>(wqkv, wproj);
    xsplit<<<(BT * CDIM * 256) / 256, 256>>>(x);
    gemm_f3<0><<<dim3(32, 18), 256, G_SMEM>>>(nullptr, nullptr);
    rope_k<<<(NB * NM * SLEN * 32) / 256, 256>>>();
    flash_tc<<<dim3(16, 24), 256, FS_TOTAL>>>();
    gemm_f3<1><<<dim3(32, 6), 256, G_SMEM>>>(x, out);
}

// round 13
// speedup vs baseline: 1.1084x; 1.0858x over previous
#include <cuda_runtime.h>
#include <cuda_fp16.h>
#include <math.h>
#include <cstdint>

// ---------------------------------------------------------------------------
// VideoAttention: b=2, t=8, C=768, h=w=16 -> hw=256, S=2048, heads=12, c=64
// 3xFP16 split precision (fp16 hi/lo, fp32 accumulate, drop lo*lo):
//   K1 norm_k    : EDM2 MP weight norm -> fp16 hi/lo weight planes
//   K2 xsplit    : x -> fp16 hi/lo planes
//   K3 gemm_f3<0>: m16n8k16 f16 HMMA GEMM -> q,k fp32; V split [bm][c][s] f16
//   K4 rope_k    : rotary; k -> fp16 hi/lo split
//   K5 flash_tc  : block-causal flash attention, 3xFP16 HMMA, 64-key chunks
//   K6 gemm_f3<1>: proj GEMM + mp_sum residual -> out
// m16n8k16 = 2048 MACs/instr (2x tf32 m16n8k8) -> halved MMA instruction count.
// ---------------------------------------------------------------------------

#define NB   2
#define NT   8
#define NM   12
#define HD   64
#define C3   2304
#define CDIM 768
#define SLEN 2048
#define BT   16
#define XSTRIDE 196608   // 768*256

__device__ float g_q[NB * NM * SLEN * HD];
__device__ float g_k[NB * NM * SLEN * HD];
__device__ __half g_kh[NB * NM * SLEN * HD], g_kl[NB * NM * SLEN * HD];
__device__ __half g_vh[NB * NM * SLEN * HD], g_vl[NB * NM * SLEN * HD]; // [bm][c][s]
__device__ __half g_wqh[C3 * CDIM],  g_wql[C3 * CDIM];
__device__ __half g_wph[CDIM * CDIM], g_wpl[CDIM * CDIM];
__device__ __half g_xh[BT * CDIM * 256], g_xl[BT * CDIM * 256];
__device__ __half g_yh[BT * CDIM * 256], g_yl[BT * CDIM * 256];

// ======================= helpers ===================
__device__ __forceinline__ uint32_t smem_to_u32(const void* p) {
    uint32_t a;
    asm("{ .reg .u64 t; cvta.to.shared.u64 t, %1; cvt.u32.u64 %0, t; }" : "=r"(a) : "l"(p));
    return a;
}
__device__ __forceinline__ float lds_f32(uint32_t addr) {
    float v;
    asm volatile("ld.shared.f32 %0, [%1];" : "=f"(v) : "r"(addr));
    return v;
}
__device__ __forceinline__ void sts_f32(uint32_t addr, float v) {
    asm volatile("st.shared.f32 [%0], %1;" :: "r"(addr), "f"(v));
}
__device__ __forceinline__ void sts_u32(uint32_t addr, uint32_t v) {
    asm volatile("st.shared.b32 [%0], %1;" :: "r"(addr), "r"(v));
}
__device__ __forceinline__ void cp16(uint32_t dst, const void* src) {
    asm volatile("cp.async.cg.shared.global [%0], [%1], 16;" :: "r"(dst), "l"(src));
}
#define CP_COMMIT() asm volatile("cp.async.commit_group;" ::: "memory")
#define CP_WAIT(n)  asm volatile("cp.async.wait_group %0;" :: "n"(n) : "memory")

__device__ __forceinline__ void ldsm4(uint32_t (&r)[4], uint32_t addr) {
    asm volatile("ldmatrix.sync.aligned.m8n8.x4.shared.b16 {%0,%1,%2,%3}, [%4];"
                 : "=r"(r[0]), "=r"(r[1]), "=r"(r[2]), "=r"(r[3]) : "r"(addr));
}
__device__ __forceinline__ void ldsm4t(uint32_t (&r)[4], uint32_t addr) {
    asm volatile("ldmatrix.sync.aligned.m8n8.x4.trans.shared.b16 {%0,%1,%2,%3}, [%4];"
                 : "=r"(r[0]), "=r"(r[1]), "=r"(r[2]), "=r"(r[3]) : "r"(addr));
}
__device__ __forceinline__ void mma_f16(float (&d)[4], const uint32_t (&a)[4],
                                        uint32_t b0, uint32_t b1) {
    asm volatile("mma.sync.aligned.m16n8k16.row.col.f32.f16.f16.f32 "
                 "{%0,%1,%2,%3}, {%4,%5,%6,%7}, {%8,%9}, {%0,%1,%2,%3};"
                 : "+f"(d[0]), "+f"(d[1]), "+f"(d[2]), "+f"(d[3])
                 : "r"(a[0]), "r"(a[1]), "r"(a[2]), "r"(a[3]), "r"(b0), "r"(b1));
}
// fp16 split: a = hi + lo (hi = rn_f16(a), lo = rn_f16(a - hi))
__device__ __forceinline__ void h_split(float a, __half& h, __half& l) {
    h = __float2half_rn(a);
    l = __float2half_rn(a - __half2float(h));
}
// split two floats, pack into h-pair and l-pair words
__device__ __forceinline__ void h_split_pack(float a, float b, uint32_t& h, uint32_t& l) {
    __half ha, la, hb, lb;
    h_split(a, ha, la);
    h_split(b, hb, lb);
    h = (uint32_t)__half_as_ushort(ha) | ((uint32_t)__half_as_ushort(hb) << 16);
    l = (uint32_t)__half_as_ushort(la) | ((uint32_t)__half_as_ushort(lb) << 16);
}

// ---------------- K1: weight normalization -> fp16 hi/lo planes ------------
__global__ __launch_bounds__(256) void norm_k(const float* __restrict__ wqkv,
                                              const float* __restrict__ wproj) {
    int row = blockIdx.x;
    const float* src;
    __half *dh, *dl;
    if (row < C3) { src = wqkv + row * CDIM; dh = g_wqh + row * CDIM; dl = g_wql + row * CDIM; }
    else { src = wproj + (row - C3) * CDIM; dh = g_wph + (row - C3) * CDIM; dl = g_wpl + (row - C3) * CDIM; }

    float ss = 0.f;
    for (int i = threadIdx.x; i < CDIM; i += 256) { float v = src[i]; ss = fmaf(v, v, ss); }
    #pragma unroll
    for (int off = 16; off; off >>= 1) ss += __shfl_xor_sync(0xffffffffu, ss, off);

    __shared__ float sred[8];
    __shared__ float sscale;
    if ((threadIdx.x & 31) == 0) sred[threadIdx.x >> 5] = ss;
    __syncthreads();
    if (threadIdx.x == 0) {
        float t = 0.f;
        #pragma unroll
        for (int i = 0; i < 8; i++) t += sred[i];
        sscale = 1.0f / (sqrtf(768.0f) * 1e-4f + sqrtf(t));
    }
    __syncthreads();
    float sc = sscale;
    for (int i = threadIdx.x; i < CDIM; i += 256) {
        __half h, l;
        h_split(src[i] * sc, h, l);
        dh[i] = h; dl[i] = l;
    }
}

// ---------------- K2: elementwise x -> fp16 hi/lo planes -------------------
__global__ __launch_bounds__(256) void xsplit(const float* __restrict__ x) {
    int i = blockIdx.x * 256 + threadIdx.x;
    __half h, l;
    h_split(x[i], h, l);
    g_xh[i] = h; g_xl[i] = l;
}

// ---------------- K3/K6: 3xFP16 HMMA GEMM, 128x128 tile, k-chunk 64 --------
// smem/stage: Ah|Al ([128 rows][144B: 64 f16 + pad]) + Bh|Bl ([64 k][272B: 128 f16 + pad])
#define GA_ROW 144
#define GB_ROW 272
#define GA_PLANE 18432   // 128*144
#define GB_PLANE 17408   // 64*272
#define G_STAGE  71680
#define G_SMEM   143360

template <int EPI>
__global__ __launch_bounds__(256) void gemm_f3(const float* __restrict__ Xres,
                                               float* __restrict__ Out) {
    extern __shared__ char smem[];
    const uint32_t sb = smem_to_u32(smem);
    const int tid = threadIdx.x, wid = tid >> 5, lid = tid & 31;
    const int o0 = blockIdx.y * 128;
    const int n0 = blockIdx.x * 128;
    const int bt = n0 >> 8;
    const int pb = n0 & 255;

    const __half* Awh = (EPI == 0 ? g_wqh : g_wph) + o0 * CDIM;
    const __half* Awl = (EPI == 0 ? g_wql : g_wpl) + o0 * CDIM;
    const __half* Bgh = (EPI == 0 ? g_xh : g_yh) + bt * XSTRIDE + pb;
    const __half* Bgl = (EPI == 0 ? g_xl : g_yl) + bt * XSTRIDE + pb;

    float acc[2][8][4];
    #pragma unroll
    for (int mi = 0; mi < 2; mi++)
        #pragma unroll
        for (int ni = 0; ni < 8; ni++)
            #pragma unroll
            for (int d = 0; d < 4; d++) acc[mi][ni][d] = 0.f;

    const int wr = wid & 3, wc = wid >> 2;
    const int g = lid >> 2, tg = lid & 3;
    const int r8 = lid & 7;
    // A frag (non-trans x4): rows (lid&15), k-half (+16B) by lid>>4
    const uint32_t aoff = (uint32_t)((lid & 15) * GA_ROW + ((lid >> 4) & 1) * 16);
    // B frag (trans x4): k-rows +8 by bit3, n-col +8 elems (16B) by bit4
    const uint32_t bk8 = (uint32_t)(((lid >> 3) & 1) * 8);
    const uint32_t bn8 = (uint32_t)(((lid >> 4) & 1) * 16);

    auto copy_stage = [&](int st, int kc) {
        uint32_t s0 = sb + st * G_STAGE;
        #pragma unroll
        for (int i = 0; i < 4; i++) {
            int idx = tid + i * 256;
            int row = idx >> 3, u = idx & 7;          // A: 128 rows x 8 segs
            uint32_t dA = s0 + row * GA_ROW + u * 16;
            cp16(dA,            Awh + row * CDIM + kc + u * 8);
            cp16(dA + GA_PLANE, Awl + row * CDIM + kc + u * 8);
            int k = idx >> 4, u2 = idx & 15;          // B: 64 k-rows x 16 segs
            uint32_t dB = s0 + 2 * GA_PLANE + k * GB_ROW + u2 * 16;
            cp16(dB,            Bgh + (kc + k) * 256 + u2 * 8);
            cp16(dB + GB_PLANE, Bgl + (kc + k) * 256 + u2 * 8);
        }
        CP_COMMIT();
    };

    copy_stage(0, 0);
    int st = 0;
    for (int kc = 0; kc < CDIM; kc += 64, st ^= 1) {
        if (kc + 64 < CDIM) {
            copy_stage(st ^ 1, kc + 64);
            CP_WAIT(1);
        } else {
            CP_WAIT(0);
        }
        __syncthreads();

        const uint32_t sAh = sb + st * G_STAGE;
        const uint32_t sAl = sAh + GA_PLANE;
        const uint32_t sBh = sAh + 2 * GA_PLANE;
        const uint32_t sBl = sBh + GB_PLANE;
        #pragma unroll
        for (int ks = 0; ks < 4; ks++) {             // k-steps of 16
            uint32_t ah[2][4], al[2][4];
            #pragma unroll
            for (int mi = 0; mi < 2; mi++) {
                uint32_t rbase = (uint32_t)((wr * 32 + mi * 16) * GA_ROW) + aoff + ks * 32;
                ldsm4(ah[mi], sAh + rbase);
                ldsm4(al[mi], sAl + rbase);
            }
            const uint32_t krow = (uint32_t)((ks * 16 + bk8 + r8) * GB_ROW);
            #pragma unroll
            for (int nj = 0; nj < 4; nj++) {
                uint32_t boff = krow + (uint32_t)((wc * 64 + nj * 16) * 2) + bn8;
                uint32_t bh[4], bl[4];
                ldsm4t(bh, sBh + boff);
                ldsm4t(bl, sBl + boff);
                #pragma unroll
                for (int mi = 0; mi < 2; mi++) {
                    mma_f16(acc[mi][2 * nj],     ah[mi], bh[0], bh[1]);
                    mma_f16(acc[mi][2 * nj + 1], ah[mi], bh[2], bh[3]);
                    mma_f16(acc[mi][2 * nj],     ah[mi], bl[0], bl[1]);
                    mma_f16(acc[mi][2 * nj + 1], ah[mi], bl[2], bl[3]);
                    mma_f16(acc[mi][2 * nj],     al[mi], bh[0], bh[1]);
                    mma_f16(acc[mi][2 * nj + 1], al[mi], bh[2], bh[3]);
                }
            }
        }
        __syncthreads();
    }

    const int cB = tg * 2;

    if (EPI == 0) {
        const int qi = blockIdx.y / 6;
        const int rem0 = o0 - qi * CDIM + wr * 32;
        const int bb = bt >> 3, ti = bt & 7;
        #pragma unroll
        for (int mi = 0; mi < 2; mi++)
            #pragma unroll
            for (int dd = 0; dd < 2; dd++) {
                int rem = rem0 + mi * 16 + g + dd * 8;
                int mh = rem >> 6, cc = rem & 63;
                if (qi < 2) {
                    float* dst = (qi == 0) ? g_q : g_k;
                    int rowbase = ((bb * NM + mh) * SLEN + ti * 256 + pb) * HD + cc;
                    #pragma unroll
                    for (int ni = 0; ni < 8; ni++) {
                        int p = wc * 64 + ni * 8 + cB;
                        dst[rowbase + p * HD]       = acc[mi][ni][dd * 2];
                        dst[rowbase + (p + 1) * HD] = acc[mi][ni][dd * 2 + 1];
                    }
                } else {
                    // V: fp16 split + transposed layout [bm][c][s]
                    int vbase = ((bb * NM + mh) * HD + cc) * SLEN + ti * 256 + pb;
                    #pragma unroll
                    for (int ni = 0; ni < 8; ni++) {
                        int p = wc * 64 + ni * 8 + cB;
                        __half h0, l0x, h1, l1x;
                        h_split(acc[mi][ni][dd * 2], h0, l0x);
                        h_split(acc[mi][ni][dd * 2 + 1], h1, l1x);
                        g_vh[vbase + p] = h0;     g_vh[vbase + p + 1] = h1;
                        g_vl[vbase + p] = l0x;    g_vl[vbase + p + 1] = l1x;
                    }
                }
            }
    } else {
        const float c1 = 0.9191450300180578f;   // 0.7 / sqrt(0.58)
        const float c2 = 0.3939192985791676f;   // 0.3 / sqrt(0.58)
        #pragma unroll
        for (int mi = 0; mi < 2; mi++)
            #pragma unroll
            for (int dd = 0; dd < 2; dd++) {
                int o = o0 + wr * 32 + mi * 16 + g + dd * 8;
                int ib = bt * XSTRIDE + o * 256 + pb + wc * 64 + cB;
                #pragma unroll
                for (int ni = 0; ni < 8; ni++) {
                    int idx = ib + ni * 8;
                    Out[idx]     = Xres[idx] * c1 + acc[mi][ni][dd * 2] * c2;
                    Out[idx + 1] = Xres[idx + 1] * c1 + acc[mi][ni][dd * 2 + 1] * c2;
                }
            }
    }
}

// ---------------- K4: RoPE over frame index; K -> fp16 split ----------------
__global__ __launch_bounds__(256) void rope_k() {
    int idx = blockIdx.x * 256 + threadIdx.x;
    int d2 = idx & 31;
    int s = (idx >> 5) & 2047;
    int bm = idx >> 16;
    int ti = s >> 8;
    float ang = (float)ti * __powf(10000.0f, -(float)d2 * (1.0f / 32.0f));
    float sn, cs;
    __sincosf(ang, &sn, &cs);
    int base = (bm * SLEN + s) * HD + d2;
    float q1 = g_q[base], q2 = g_q[base + 32];
    g_q[base]      = q1 * cs - q2 * sn;
    g_q[base + 32] = q1 * sn + q2 * cs;
    float k1 = g_k[base], k2 = g_k[base + 32];
    float kr1 = k1 * cs - k2 * sn;
    float kr2 = k1 * sn + k2 * cs;
    __half h, l;
    h_split(kr1, h, l); g_kh[base] = h;      g_kl[base] = l;
    h_split(kr2, h, l); g_kh[base + 32] = h; g_kl[base + 32] = l;
}

// ---------------- K5: block-causal flash attention, 3xFP16, 64-key chunks --
// grid (16 q-tiles of 128 rows heavy-first, 24 bm), 256 threads / 8 warps.
// K planes [key 64][144B: 64 f16 + pad]; V planes [c 64][144B: 64 keys f16 + pad].
#define FK_ROW 144
#define FK_PLANE 9216    // 64*144
#define FS_STAGE 36864   // 4 planes
#define FS_P 73728       // 2 stages
#define FS_TOTAL (FS_P + 8 * 4608)   // 110592

__global__ __launch_bounds__(256) void flash_tc() {
    extern __shared__ char fsm[];
    const uint32_t sb = smem_to_u32(fsm);
    const int tid = threadIdx.x, w = tid >> 5, lid = tid & 31;
    const int g = lid >> 2, tg = lid & 3;
    const int r8 = lid & 7;
    const int qt = 15 - blockIdx.x;      // heavy causal tiles first
    const int bm = blockIdx.y;
    const int s0 = qt * 128;
    const int fr = qt >> 1;
    const int nch = (fr + 1) * 4;        // 64-key chunks

    const uint32_t PSh = sb + FS_P + w * 4608;
    const uint32_t PSl = PSh + 2304;     // 16 rows x 144B each plane

    const float* Qg = g_q + (bm * SLEN + s0 + w * 16) * HD;
    const __half* Khg = g_kh + bm * SLEN * HD;
    const __half* Klg = g_kl + bm * SLEN * HD;
    const __half* Vhg = g_vh + bm * HD * SLEN;   // [c][s]
    const __half* Vlg = g_vl + bm * HD * SLEN;

    // B-frag (non-trans x4): row +8 by bit4, col-half +8 elems (16B) by bit3
    const uint32_t brow8 = (uint32_t)(((lid >> 4) & 1) * 8);
    const uint32_t bcol8 = (uint32_t)(((lid >> 3) & 1) * 16);
    // P A-frag (non-trans x4)
    const uint32_t poff = (uint32_t)((lid & 15) * FK_ROW + ((lid >> 4) & 1) * 16);

    // register-resident Q fragments (fp16 split, packed pairs)
    uint32_t qh[4][4], ql[4][4];
    #pragma unroll
    for (int ks = 0; ks < 4; ks++) {
        int c0 = ks * 16 + 2 * tg;
        h_split_pack(Qg[g * 64 + c0],           Qg[g * 64 + c0 + 1],           qh[ks][0], ql[ks][0]);
        h_split_pack(Qg[(g + 8) * 64 + c0],     Qg[(g + 8) * 64 + c0 + 1],     qh[ks][1], ql[ks][1]);
        h_split_pack(Qg[g * 64 + c0 + 8],       Qg[g * 64 + c0 + 9],           qh[ks][2], ql[ks][2]);
        h_split_pack(Qg[(g + 8) * 64 + c0 + 8], Qg[(g + 8) * 64 + c0 + 9],     qh[ks][3], ql[ks][3]);
    }

    float o[8][4];
    #pragma unroll
    for (int ct = 0; ct < 8; ct++)
        #pragma unroll
        for (int d = 0; d < 4; d++) o[ct][d] = 0.f;
    float m0 = -1e30f, m1 = -1e30f, l0 = 0.f, l1 = 0.f;

    auto stage = [&](int st, int k0) {
        uint32_t b0 = sb + st * FS_STAGE;
        #pragma unroll
        for (int i = 0; i < 2; i++) {
            int idx = tid + i * 256;          // 0..511
            int key = idx >> 3, u = idx & 7;
            uint32_t dK = b0 + key * FK_ROW + u * 16;
            const __half* sK = Khg + (k0 + key) * 64 + u * 8;
            cp16(dK,            sK);
            cp16(dK + FK_PLANE, Klg + (k0 + key) * 64 + u * 8);
            uint32_t dV = b0 + 2 * FK_PLANE + key * FK_ROW + u * 16;   // key -> channel row
            const __half* sV = Vhg + key * SLEN + k0 + u * 8;
            cp16(dV,            sV);
            cp16(dV + FK_PLANE, Vlg + key * SLEN + k0 + u * 8);
        }
        CP_COMMIT();
    };

    stage(0, 0);
    int st = 0;
    for (int ic = 0; ic < nch; ic++, st ^= 1) {
        if (ic + 1 < nch) {
            stage(st ^ 1, (ic + 1) * 64);
            CP_WAIT(1);
        } else {
            CP_WAIT(0);
        }
        __syncthreads();
        const uint32_t bKh = sb + st * FS_STAGE;
        const uint32_t bKl = bKh + FK_PLANE;
        const uint32_t bVh = bKh + 2 * FK_PLANE;
        const uint32_t bVl = bVh + FK_PLANE;

        // ---- S = Q K^T (16 rows x 64 keys per warp) ----
        float s[8][4];
        #pragma unroll
        for (int nt = 0; nt < 8; nt++)
            #pragma unroll
            for (int d = 0; d < 4; d++) s[nt][d] = 0.f;
        #pragma unroll
        for (int ks = 0; ks < 4; ks++) {             // channel k-steps of 16
            const uint32_t ck = (uint32_t)(ks * 32) + bcol8;
            #pragma unroll
            for (int nj = 0; nj < 4; nj++) {
                uint32_t off = (uint32_t)((nj * 16 + brow8 + r8) * FK_ROW) + ck;
                uint32_t kh[4], kl[4];
                ldsm4(kh, bKh + off);
                ldsm4(kl, bKl + off);
                mma_f16(s[2 * nj],     qh[ks], kh[0], kh[1]);
                mma_f16(s[2 * nj + 1], qh[ks], kh[2], kh[3]);
                mma_f16(s[2 * nj],     qh[ks], kl[0], kl[1]);
                mma_f16(s[2 * nj + 1], qh[ks], kl[2], kl[3]);
                mma_f16(s[2 * nj],     ql[ks], kh[0], kh[1]);
                mma_f16(s[2 * nj + 1], ql[ks], kh[2], kh[3]);
            }
        }

        // ---- online softmax (rows g, g+8; reduce over the 4 tg lanes) ----
        float mx0 = -1e30f, mx1 = -1e30f;
        #pragma unroll
        for (int nt = 0; nt < 8; nt++) {
            #pragma unroll
            for (int d = 0; d < 4; d++) s[nt][d] *= 0.125f;
            mx0 = fmaxf(mx0, fmaxf(s[nt][0], s[nt][1]));
            mx1 = fmaxf(mx1, fmaxf(s[nt][2], s[nt][3]));
        }
        mx0 = fmaxf(mx0, __shfl_xor_sync(0xffffffffu, mx0, 1));
        mx0 = fmaxf(mx0, __shfl_xor_sync(0xffffffffu, mx0, 2));
        mx1 = fmaxf(mx1, __shfl_xor_sync(0xffffffffu, mx1, 1));
        mx1 = fmaxf(mx1, __shfl_xor_sync(0xffffffffu, mx1, 2));
        float mn0 = fmaxf(m0, mx0), mn1 = fmaxf(m1, mx1);
        float cr0 = __expf(m0 - mn0), cr1 = __expf(m1 - mn1);
        m0 = mn0; m1 = mn1;
        float rs0 = 0.f, rs1 = 0.f;
        #pragma unroll
        for (int nt = 0; nt < 8; nt++) {
            s[nt][0] = __expf(s[nt][0] - mn0);
            s[nt][1] = __expf(s[nt][1] - mn0);
            s[nt][2] = __expf(s[nt][2] - mn1);
            s[nt][3] = __expf(s[nt][3] - mn1);
            rs0 += s[nt][0] + s[nt][1];
            rs1 += s[nt][2] + s[nt][3];
        }
        rs0 += __shfl_xor_sync(0xffffffffu, rs0, 1);
        rs0 += __shfl_xor_sync(0xffffffffu, rs0, 2);
        rs1 += __shfl_xor_sync(0xffffffffu, rs1, 1);
        rs1 += __shfl_xor_sync(0xffffffffu, rs1, 2);
        l0 = l0 * cr0 + rs0;
        l1 = l1 * cr1 + rs1;
        #pragma unroll
        for (int ct = 0; ct < 8; ct++) {
            o[ct][0] *= cr0; o[ct][1] *= cr0;
            o[ct][2] *= cr1; o[ct][3] *= cr1;
        }

        // ---- stage P as packed fp16 hi/lo planes (16 rows x 64 keys) ----
        #pragma unroll
        for (int nt = 0; nt < 8; nt++) {
            uint32_t h01, l01, h23, l23;
            h_split_pack(s[nt][0], s[nt][1], h01, l01);
            h_split_pack(s[nt][2], s[nt][3], h23, l23);
            uint32_t cofs = (uint32_t)(nt * 16 + tg * 4);
            sts_u32(PSh + g * FK_ROW + cofs,       h01);
            sts_u32(PSh + (g + 8) * FK_ROW + cofs, h23);
            sts_u32(PSl + g * FK_ROW + cofs,       l01);
            sts_u32(PSl + (g + 8) * FK_ROW + cofs, l23);
        }
        __syncwarp();

        // ---- O += P V (key k-steps of 16) ----
        #pragma unroll
        for (int kk = 0; kk < 4; kk++) {
            uint32_t ph[4], pl[4];
            ldsm4(ph, PSh + poff + kk * 32);
            ldsm4(pl, PSl + poff + kk * 32);
            const uint32_t kb = (uint32_t)(kk * 32) + bcol8;
            #pragma unroll
            for (int cj = 0; cj < 4; cj++) {
                uint32_t off = (uint32_t)((cj * 16 + brow8 + r8) * FK_ROW) + kb;
                uint32_t vh[4], vl[4];
                ldsm4(vh, bVh + off);
                ldsm4(vl, bVl + off);
                mma_f16(o[2 * cj],     ph, vh[0], vh[1]);
                mma_f16(o[2 * cj + 1], ph, vh[2], vh[3]);
                mma_f16(o[2 * cj],     ph, vl[0], vl[1]);
                mma_f16(o[2 * cj + 1], ph, vl[2], vl[3]);
                mma_f16(o[2 * cj],     pl, vh[0], vh[1]);
                mma_f16(o[2 * cj + 1], pl, vh[2], vh[3]);
            }
        }
        __syncthreads();
    }

    // ---- epilogue: O /= l, transpose via smem (fp32), split on write ----
    const uint32_t TH = sb;              // 64 ch x 528B fp32 rows (reuse stages)
    float li0 = 1.f / l0, li1 = 1.f / l1;
    #pragma unroll
    for (int ct = 0; ct < 8; ct++) {
        int c0 = ct * 8 + 2 * tg;
        int row0 = w * 16 + g, row1 = row0 + 8;
        sts_f32(TH + c0 * 528 + row0 * 4,       o[ct][0] * li0);
        sts_f32(TH + (c0 + 1) * 528 + row0 * 4, o[ct][1] * li0);
        sts_f32(TH + c0 * 528 + row1 * 4,       o[ct][2] * li1);
        sts_f32(TH + (c0 + 1) * 528 + row1 * 4, o[ct][3] * li1);
    }
    __syncthreads();
    const int bb = bm / NM, mh = bm - bb * NM;
    const int bt = bb * NT + fr;
    const int p0 = (qt & 1) * 128;
    const int obase = bt * XSTRIDE + mh * 256 + p0;
    #pragma unroll
    for (int it = 0; it < 32; it++) {
        int idx = tid + it * 256;       // 0..8191
        int c = idx >> 7, rr = idx & 127;
        float v = lds_f32(TH + c * 528 + rr * 4);
        __half h, l;
        h_split(v, h, l);
        g_yh[obase + c * 3072 + rr] = h;
        g_yl[obase + c * 3072 + rr] = l;
    }
}

// ---------------- launch ----------------
extern "C" void kernel_launch(void* const* d_in, const int* in_sizes, int n_in,
                              void* d_out, int out_size) {
    const float* x = (const float*)d_in[0];
    const float* wqkv = (const float*)d_in[1];
    const float* wproj = (const float*)d_in[2];
    float* out = (float*)d_out;

    cudaFuncSetAttribute(gemm_f3<0>, cudaFuncAttributeMaxDynamicSharedMemorySize, G_SMEM);
    cudaFuncSetAttribute(gemm_f3<1>, cudaFuncAttributeMaxDynamicSharedMemorySize, G_SMEM);
    cudaFuncSetAttribute(flash_tc, cudaFuncAttributeMaxDynamicSharedMemorySize, FS_TOTAL);

    norm_k<<<C3 + CDIM, 256>>>(wqkv, wproj);
    xsplit<<<(BT * CDIM * 256) / 256, 256>>>(x);
    gemm_f3<0><<<dim3(32, 18), 256, G_SMEM>>>(nullptr, nullptr);
    rope_k<<<(NB * NM * SLEN * 32) / 256, 256>>>();
    flash_tc<<<dim3(16, 24), 256, FS_TOTAL>>>();
    gemm_f3<1><<<dim3(32, 6), 256, G_SMEM>>>(x, out);
}

// round 15
// speedup vs baseline: 1.9812x; 1.7875x over previous
#include <cuda_runtime.h>
#include <cuda_fp16.h>
#include <math.h>
#include <cstdint>

// ---------------------------------------------------------------------------
// VideoAttention: b=2, t=8, C=768, h=w=16 -> hw=256, S=2048, heads=12, c=64
// 3xFP16 split precision for GEMMs and S=QK^T; PV uses SINGLE-TERM Ph*Vh
// (softmax weights in [0,1] -> dropping lo-planes costs ~5e-4 relative on the
// attention output, ~1-2e-4 on the final result; tolerance is 1e-3).
//   K1 norm_k    : EDM2 MP weight norm -> fp16 hi/lo weight planes
//   K2 xsplit    : x -> fp16 hi/lo planes
//   K3 gemm_f3<0>: m16n8k16 f16 HMMA GEMM -> q,k fp32; V fp16 (hi only) [bm][c][s]
//   K4 rope_k    : rotary; k -> fp16 hi/lo split
//   K5 flash_tc  : block-causal flash attention, 64-key chunks
//   K6 gemm_f3<1>: proj GEMM + mp_sum residual -> out
// ---------------------------------------------------------------------------

#define NB   2
#define NT   8
#define NM   12
#define HD   64
#define C3   2304
#define CDIM 768
#define SLEN 2048
#define BT   16
#define XSTRIDE 196608   // 768*256

__device__ float g_q[NB * NM * SLEN * HD];
__device__ float g_k[NB * NM * SLEN * HD];
__device__ __half g_kh[NB * NM * SLEN * HD], g_kl[NB * NM * SLEN * HD];
__device__ __half g_vh[NB * NM * SLEN * HD];                 // [bm][c][s], hi only
__device__ __half g_wqh[C3 * CDIM],  g_wql[C3 * CDIM];
__device__ __half g_wph[CDIM * CDIM], g_wpl[CDIM * CDIM];
__device__ __half g_xh[BT * CDIM * 256], g_xl[BT * CDIM * 256];
__device__ __half g_yh[BT * CDIM * 256], g_yl[BT * CDIM * 256];

// ======================= helpers ===================
__device__ __forceinline__ uint32_t smem_to_u32(const void* p) {
    uint32_t a;
    asm("{ .reg .u64 t; cvta.to.shared.u64 t, %1; cvt.u32.u64 %0, t; }" : "=r"(a) : "l"(p));
    return a;
}
__device__ __forceinline__ float lds_f32(uint32_t addr) {
    float v;
    asm volatile("ld.shared.f32 %0, [%1];" : "=f"(v) : "r"(addr));
    return v;
}
__device__ __forceinline__ void sts_f32(uint32_t addr, float v) {
    asm volatile("st.shared.f32 [%0], %1;" :: "r"(addr), "f"(v));
}
__device__ __forceinline__ void sts_u32(uint32_t addr, uint32_t v) {
    asm volatile("st.shared.b32 [%0], %1;" :: "r"(addr), "r"(v));
}
__device__ __forceinline__ void cp16(uint32_t dst, const void* src) {
    asm volatile("cp.async.cg.shared.global [%0], [%1], 16;" :: "r"(dst), "l"(src));
}
#define CP_COMMIT() asm volatile("cp.async.commit_group;" ::: "memory")
#define CP_WAIT(n)  asm volatile("cp.async.wait_group %0;" :: "n"(n) : "memory")

__device__ __forceinline__ void ldsm4(uint32_t (&r)[4], uint32_t addr) {
    asm volatile("ldmatrix.sync.aligned.m8n8.x4.shared.b16 {%0,%1,%2,%3}, [%4];"
                 : "=r"(r[0]), "=r"(r[1]), "=r"(r[2]), "=r"(r[3]) : "r"(addr));
}
__device__ __forceinline__ void ldsm4t(uint32_t (&r)[4], uint32_t addr) {
    asm volatile("ldmatrix.sync.aligned.m8n8.x4.trans.shared.b16 {%0,%1,%2,%3}, [%4];"
                 : "=r"(r[0]), "=r"(r[1]), "=r"(r[2]), "=r"(r[3]) : "r"(addr));
}
__device__ __forceinline__ void mma_f16(float (&d)[4], const uint32_t (&a)[4],
                                        uint32_t b0, uint32_t b1) {
    asm volatile("mma.sync.aligned.m16n8k16.row.col.f32.f16.f16.f32 "
                 "{%0,%1,%2,%3}, {%4,%5,%6,%7}, {%8,%9}, {%0,%1,%2,%3};"
                 : "+f"(d[0]), "+f"(d[1]), "+f"(d[2]), "+f"(d[3])
                 : "r"(a[0]), "r"(a[1]), "r"(a[2]), "r"(a[3]), "r"(b0), "r"(b1));
}
__device__ __forceinline__ void h_split(float a, __half& h, __half& l) {
    h = __float2half_rn(a);
    l = __float2half_rn(a - __half2float(h));
}
__device__ __forceinline__ void h_split_pack(float a, float b, uint32_t& h, uint32_t& l) {
    __half ha, la, hb, lb;
    h_split(a, ha, la);
    h_split(b, hb, lb);
    h = (uint32_t)__half_as_ushort(ha) | ((uint32_t)__half_as_ushort(hb) << 16);
    l = (uint32_t)__half_as_ushort(la) | ((uint32_t)__half_as_ushort(lb) << 16);
}
__device__ __forceinline__ uint32_t h_pack(float a, float b) {
    __half ha = __float2half_rn(a), hb = __float2half_rn(b);
    return (uint32_t)__half_as_ushort(ha) | ((uint32_t)__half_as_ushort(hb) << 16);
}

// ---------------- K1: weight normalization -> fp16 hi/lo planes ------------
__global__ __launch_bounds__(256) void norm_k(const float* __restrict__ wqkv,
                                              const float* __restrict__ wproj) {
    int row = blockIdx.x;
    const float* src;
    __half *dh, *dl;
    if (row < C3) { src = wqkv + row * CDIM; dh = g_wqh + row * CDIM; dl = g_wql + row * CDIM; }
    else { src = wproj + (row - C3) * CDIM; dh = g_wph + (row - C3) * CDIM; dl = g_wpl + (row - C3) * CDIM; }

    float ss = 0.f;
    for (int i = threadIdx.x; i < CDIM; i += 256) { float v = src[i]; ss = fmaf(v, v, ss); }
    #pragma unroll
    for (int off = 16; off; off >>= 1) ss += __shfl_xor_sync(0xffffffffu, ss, off);

    __shared__ float sred[8];
    __shared__ float sscale;
    if ((threadIdx.x & 31) == 0) sred[threadIdx.x >> 5] = ss;
    __syncthreads();
    if (threadIdx.x == 0) {
        float t = 0.f;
        #pragma unroll
        for (int i = 0; i < 8; i++) t += sred[i];
        sscale = 1.0f / (sqrtf(768.0f) * 1e-4f + sqrtf(t));
    }
    __syncthreads();
    float sc = sscale;
    for (int i = threadIdx.x; i < CDIM; i += 256) {
        __half h, l;
        h_split(src[i] * sc, h, l);
        dh[i] = h; dl[i] = l;
    }
}

// ---------------- K2: elementwise x -> fp16 hi/lo planes -------------------
__global__ __launch_bounds__(256) void xsplit(const float* __restrict__ x) {
    int i = blockIdx.x * 256 + threadIdx.x;
    __half h, l;
    h_split(x[i], h, l);
    g_xh[i] = h; g_xl[i] = l;
}

// ---------------- K3/K6: 3xFP16 HMMA GEMM, 128x128 tile, k-chunk 64 --------
#define GA_ROW 144
#define GB_ROW 272
#define GA_PLANE 18432   // 128*144
#define GB_PLANE 17408   // 64*272
#define G_STAGE  71680
#define G_SMEM   143360

template <int EPI>
__global__ __launch_bounds__(256) void gemm_f3(const float* __restrict__ Xres,
                                               float* __restrict__ Out) {
    extern __shared__ char smem[];
    const uint32_t sb = smem_to_u32(smem);
    const int tid = threadIdx.x, wid = tid >> 5, lid = tid & 31;
    const int o0 = blockIdx.y * 128;
    const int n0 = blockIdx.x * 128;
    const int bt = n0 >> 8;
    const int pb = n0 & 255;

    const __half* Awh = (EPI == 0 ? g_wqh : g_wph) + o0 * CDIM;
    const __half* Awl = (EPI == 0 ? g_wql : g_wpl) + o0 * CDIM;
    const __half* Bgh = (EPI == 0 ? g_xh : g_yh) + bt * XSTRIDE + pb;
    const __half* Bgl = (EPI == 0 ? g_xl : g_yl) + bt * XSTRIDE + pb;

    float acc[2][8][4];
    #pragma unroll
    for (int mi = 0; mi < 2; mi++)
        #pragma unroll
        for (int ni = 0; ni < 8; ni++)
            #pragma unroll
            for (int d = 0; d < 4; d++) acc[mi][ni][d] = 0.f;

    const int wr = wid & 3, wc = wid >> 2;
    const int g = lid >> 2, tg = lid & 3;
    const int r8 = lid & 7;
    const uint32_t aoff = (uint32_t)((lid & 15) * GA_ROW + ((lid >> 4) & 1) * 16);
    const uint32_t bk8 = (uint32_t)(((lid >> 3) & 1) * 8);
    const uint32_t bn8 = (uint32_t)(((lid >> 4) & 1) * 16);

    auto copy_stage = [&](int st, int kc) {
        uint32_t s0 = sb + st * G_STAGE;
        #pragma unroll
        for (int i = 0; i < 4; i++) {
            int idx = tid + i * 256;
            int row = idx >> 3, u = idx & 7;
            uint32_t dA = s0 + row * GA_ROW + u * 16;
            cp16(dA,            Awh + row * CDIM + kc + u * 8);
            cp16(dA + GA_PLANE, Awl + row * CDIM + kc + u * 8);
            int k = idx >> 4, u2 = idx & 15;
            uint32_t dB = s0 + 2 * GA_PLANE + k * GB_ROW + u2 * 16;
            cp16(dB,            Bgh + (kc + k) * 256 + u2 * 8);
            cp16(dB + GB_PLANE, Bgl + (kc + k) * 256 + u2 * 8);
        }
        CP_COMMIT();
    };

    copy_stage(0, 0);
    int st = 0;
    for (int kc = 0; kc < CDIM; kc += 64, st ^= 1) {
        if (kc + 64 < CDIM) {
            copy_stage(st ^ 1, kc + 64);
            CP_WAIT(1);
        } else {
            CP_WAIT(0);
        }
        __syncthreads();

        const uint32_t sAh = sb + st * G_STAGE;
        const uint32_t sAl = sAh + GA_PLANE;
        const uint32_t sBh = sAh + 2 * GA_PLANE;
        const uint32_t sBl = sBh + GB_PLANE;
        #pragma unroll
        for (int ks = 0; ks < 4; ks++) {
            uint32_t ah[2][4], al[2][4];
            #pragma unroll
            for (int mi = 0; mi < 2; mi++) {
                uint32_t rbase = (uint32_t)((wr * 32 + mi * 16) * GA_ROW) + aoff + ks * 32;
                ldsm4(ah[mi], sAh + rbase);
                ldsm4(al[mi], sAl + rbase);
            }
            const uint32_t krow = (uint32_t)((ks * 16 + bk8 + r8) * GB_ROW);
            #pragma unroll
            for (int nj = 0; nj < 4; nj++) {
                uint32_t boff = krow + (uint32_t)((wc * 64 + nj * 16) * 2) + bn8;
                uint32_t bh[4], bl[4];
                ldsm4t(bh, sBh + boff);
                ldsm4t(bl, sBl + boff);
                #pragma unroll
                for (int mi = 0; mi < 2; mi++) {
                    mma_f16(acc[mi][2 * nj],     ah[mi], bh[0], bh[1]);
                    mma_f16(acc[mi][2 * nj + 1], ah[mi], bh[2], bh[3]);
                    mma_f16(acc[mi][2 * nj],     ah[mi], bl[0], bl[1]);
                    mma_f16(acc[mi][2 * nj + 1], ah[mi], bl[2], bl[3]);
                    mma_f16(acc[mi][2 * nj],     al[mi], bh[0], bh[1]);
                    mma_f16(acc[mi][2 * nj + 1], al[mi], bh[2], bh[3]);
                }
            }
        }
        __syncthreads();
    }

    const int cB = tg * 2;

    if (EPI == 0) {
        const int qi = blockIdx.y / 6;
        const int rem0 = o0 - qi * CDIM + wr * 32;
        const int bb = bt >> 3, ti = bt & 7;
        #pragma unroll
        for (int mi = 0; mi < 2; mi++)
            #pragma unroll
            for (int dd = 0; dd < 2; dd++) {
                int rem = rem0 + mi * 16 + g + dd * 8;
                int mh = rem >> 6, cc = rem & 63;
                if (qi < 2) {
                    float* dst = (qi == 0) ? g_q : g_k;
                    int rowbase = ((bb * NM + mh) * SLEN + ti * 256 + pb) * HD + cc;
                    #pragma unroll
                    for (int ni = 0; ni < 8; ni++) {
                        int p = wc * 64 + ni * 8 + cB;
                        dst[rowbase + p * HD]       = acc[mi][ni][dd * 2];
                        dst[rowbase + (p + 1) * HD] = acc[mi][ni][dd * 2 + 1];
                    }
                } else {
                    // V: fp16 hi only, transposed layout [bm][c][s]
                    int vbase = ((bb * NM + mh) * HD + cc) * SLEN + ti * 256 + pb;
                    #pragma unroll
                    for (int ni = 0; ni < 8; ni++) {
                        int p = wc * 64 + ni * 8 + cB;
                        g_vh[vbase + p]     = __float2half_rn(acc[mi][ni][dd * 2]);
                        g_vh[vbase + p + 1] = __float2half_rn(acc[mi][ni][dd * 2 + 1]);
                    }
                }
            }
    } else {
        const float c1 = 0.9191450300180578f;   // 0.7 / sqrt(0.58)
        const float c2 = 0.3939192985791676f;   // 0.3 / sqrt(0.58)
        #pragma unroll
        for (int mi = 0; mi < 2; mi++)
            #pragma unroll
            for (int dd = 0; dd < 2; dd++) {
                int o = o0 + wr * 32 + mi * 16 + g + dd * 8;
                int ib = bt * XSTRIDE + o * 256 + pb + wc * 64 + cB;
                #pragma unroll
                for (int ni = 0; ni < 8; ni++) {
                    int idx = ib + ni * 8;
                    Out[idx]     = Xres[idx] * c1 + acc[mi][ni][dd * 2] * c2;
                    Out[idx + 1] = Xres[idx + 1] * c1 + acc[mi][ni][dd * 2 + 1] * c2;
                }
            }
    }
}

// ---------------- K4: RoPE over frame index; K -> fp16 split ----------------
__global__ __launch_bounds__(256) void rope_k() {
    int idx = blockIdx.x * 256 + threadIdx.x;
    int d2 = idx & 31;
    int s = (idx >> 5) & 2047;
    int bm = idx >> 16;
    int ti = s >> 8;
    float ang = (float)ti * __powf(10000.0f, -(float)d2 * (1.0f / 32.0f));
    float sn, cs;
    __sincosf(ang, &sn, &cs);
    int base = (bm * SLEN + s) * HD + d2;
    float q1 = g_q[base], q2 = g_q[base + 32];
    g_q[base]      = q1 * cs - q2 * sn;
    g_q[base + 32] = q1 * sn + q2 * cs;
    float k1 = g_k[base], k2 = g_k[base + 32];
    float kr1 = k1 * cs - k2 * sn;
    float kr2 = k1 * sn + k2 * cs;
    __half h, l;
    h_split(kr1, h, l); g_kh[base] = h;      g_kl[base] = l;
    h_split(kr2, h, l); g_kh[base + 32] = h; g_kl[base + 32] = l;
}

// ---------------- K5: flash attention: 3-term S, 1-term PV -----------------
// grid (16 q-tiles of 128 rows heavy-first, 24 bm), 256 threads / 8 warps.
// smem stage: Kh|Kl ([key 64][144B]) + Vh ([c 64][144B]); 2 stages; + per-warp
// Ph plane (16 x 144B).
#define FK_ROW 144
#define FK_PLANE 9216    // 64*144
#define FS_STAGE 27648   // 3 planes
#define FS_P 55296       // 2 stages
#define FS_TOTAL (FS_P + 8 * 2304)   // 73728

__global__ __launch_bounds__(256) void flash_tc() {
    extern __shared__ char fsm[];
    const uint32_t sb = smem_to_u32(fsm);
    const int tid = threadIdx.x, w = tid >> 5, lid = tid & 31;
    const int g = lid >> 2, tg = lid & 3;
    const int r8 = lid & 7;
    const int qt = 15 - blockIdx.x;      // heavy causal tiles first
    const int bm = blockIdx.y;
    const int s0 = qt * 128;
    const int fr = qt >> 1;
    const int nch = (fr + 1) * 4;        // 64-key chunks

    const uint32_t PSh = sb + FS_P + w * 2304;

    const float* Qg = g_q + (bm * SLEN + s0 + w * 16) * HD;
    const __half* Khg = g_kh + bm * SLEN * HD;
    const __half* Klg = g_kl + bm * SLEN * HD;
    const __half* Vhg = g_vh + bm * HD * SLEN;   // [c][s]

    const uint32_t brow8 = (uint32_t)(((lid >> 4) & 1) * 8);
    const uint32_t bcol8 = (uint32_t)(((lid >> 3) & 1) * 16);
    const uint32_t poff = (uint32_t)((lid & 15) * FK_ROW + ((lid >> 4) & 1) * 16);

    // register-resident Q fragments (fp16 split, packed pairs)
    uint32_t qh[4][4], ql[4][4];
    #pragma unroll
    for (int ks = 0; ks < 4; ks++) {
        int c0 = ks * 16 + 2 * tg;
        h_split_pack(Qg[g * 64 + c0],           Qg[g * 64 + c0 + 1],       qh[ks][0], ql[ks][0]);
        h_split_pack(Qg[(g + 8) * 64 + c0],     Qg[(g + 8) * 64 + c0 + 1], qh[ks][1], ql[ks][1]);
        h_split_pack(Qg[g * 64 + c0 + 8],       Qg[g * 64 + c0 + 9],       qh[ks][2], ql[ks][2]);
        h_split_pack(Qg[(g + 8) * 64 + c0 + 8], Qg[(g + 8) * 64 + c0 + 9], qh[ks][3], ql[ks][3]);
    }

    float o[8][4];
    #pragma unroll
    for (int ct = 0; ct < 8; ct++)
        #pragma unroll
        for (int d = 0; d < 4; d++) o[ct][d] = 0.f;
    float m0 = -1e30f, m1 = -1e30f, l0 = 0.f, l1 = 0.f;

    auto stage = [&](int st, int k0) {
        uint32_t b0 = sb + st * FS_STAGE;
        #pragma unroll
        for (int i = 0; i < 2; i++) {
            int idx = tid + i * 256;          // 0..511
            int key = idx >> 3, u = idx & 7;
            uint32_t dK = b0 + key * FK_ROW + u * 16;
            cp16(dK,            Khg + (k0 + key) * 64 + u * 8);
            cp16(dK + FK_PLANE, Klg + (k0 + key) * 64 + u * 8);
            uint32_t dV = b0 + 2 * FK_PLANE + key * FK_ROW + u * 16;   // key -> channel row
            cp16(dV, Vhg + key * SLEN + k0 + u * 8);
        }
        CP_COMMIT();
    };

    stage(0, 0);
    int st = 0;
    for (int ic = 0; ic < nch; ic++, st ^= 1) {
        if (ic + 1 < nch) {
            stage(st ^ 1, (ic + 1) * 64);
            CP_WAIT(1);
        } else {
            CP_WAIT(0);
        }
        __syncthreads();
        const uint32_t bKh = sb + st * FS_STAGE;
        const uint32_t bKl = bKh + FK_PLANE;
        const uint32_t bVh = bKh + 2 * FK_PLANE;

        // ---- S = Q K^T (16 rows x 64 keys per warp, 3-term) ----
        float s[8][4];
        #pragma unroll
        for (int nt = 0; nt < 8; nt++)
            #pragma unroll
            for (int d = 0; d < 4; d++) s[nt][d] = 0.f;
        #pragma unroll
        for (int ks = 0; ks < 4; ks++) {
            const uint32_t ck = (uint32_t)(ks * 32) + bcol8;
            #pragma unroll
            for (int nj = 0; nj < 4; nj++) {
                uint32_t off = (uint32_t)((nj * 16 + brow8 + r8) * FK_ROW) + ck;
                uint32_t kh[4], kl[4];
                ldsm4(kh, bKh + off);
                ldsm4(kl, bKl + off);
                mma_f16(s[2 * nj],     qh[ks], kh[0], kh[1]);
                mma_f16(s[2 * nj + 1], qh[ks], kh[2], kh[3]);
                mma_f16(s[2 * nj],     qh[ks], kl[0], kl[1]);
                mma_f16(s[2 * nj + 1], qh[ks], kl[2], kl[3]);
                mma_f16(s[2 * nj],     ql[ks], kh[0], kh[1]);
                mma_f16(s[2 * nj + 1], ql[ks], kh[2], kh[3]);
            }
        }

        // ---- online softmax (rows g, g+8; reduce over the 4 tg lanes) ----
        float mx0 = -1e30f, mx1 = -1e30f;
        #pragma unroll
        for (int nt = 0; nt < 8; nt++) {
            #pragma unroll
            for (int d = 0; d < 4; d++) s[nt][d] *= 0.125f;
            mx0 = fmaxf(mx0, fmaxf(s[nt][0], s[nt][1]));
            mx1 = fmaxf(mx1, fmaxf(s[nt][2], s[nt][3]));
        }
        mx0 = fmaxf(mx0, __shfl_xor_sync(0xffffffffu, mx0, 1));
        mx0 = fmaxf(mx0, __shfl_xor_sync(0xffffffffu, mx0, 2));
        mx1 = fmaxf(mx1, __shfl_xor_sync(0xffffffffu, mx1, 1));
        mx1 = fmaxf(mx1, __shfl_xor_sync(0xffffffffu, mx1, 2));
        float mn0 = fmaxf(m0, mx0), mn1 = fmaxf(m1, mx1);
        float cr0 = __expf(m0 - mn0), cr1 = __expf(m1 - mn1);
        m0 = mn0; m1 = mn1;
        float rs0 = 0.f, rs1 = 0.f;
        #pragma unroll
        for (int nt = 0; nt < 8; nt++) {
            s[nt][0] = __expf(s[nt][0] - mn0);
            s[nt][1] = __expf(s[nt][1] - mn0);
            s[nt][2] = __expf(s[nt][2] - mn1);
            s[nt][3] = __expf(s[nt][3] - mn1);
            rs0 += s[nt][0] + s[nt][1];
            rs1 += s[nt][2] + s[nt][3];
        }
        rs0 += __shfl_xor_sync(0xffffffffu, rs0, 1);
        rs0 += __shfl_xor_sync(0xffffffffu, rs0, 2);
        rs1 += __shfl_xor_sync(0xffffffffu, rs1, 1);
        rs1 += __shfl_xor_sync(0xffffffffu, rs1, 2);
        l0 = l0 * cr0 + rs0;
        l1 = l1 * cr1 + rs1;
        #pragma unroll
        for (int ct = 0; ct < 8; ct++) {
            o[ct][0] *= cr0; o[ct][1] *= cr0;
            o[ct][2] *= cr1; o[ct][3] *= cr1;
        }

        // ---- stage P as packed fp16 (hi only; 16 rows x 64 keys) ----
        #pragma unroll
        for (int nt = 0; nt < 8; nt++) {
            uint32_t cofs = (uint32_t)(nt * 16 + tg * 4);
            sts_u32(PSh + g * FK_ROW + cofs,       h_pack(s[nt][0], s[nt][1]));
            sts_u32(PSh + (g + 8) * FK_ROW + cofs, h_pack(s[nt][2], s[nt][3]));
        }
        __syncwarp();

        // ---- O += Ph Vh (single-term; key k-steps of 16) ----
        #pragma unroll
        for (int kk = 0; kk < 4; kk++) {
            uint32_t ph[4];
            ldsm4(ph, PSh + poff + kk * 32);
            const uint32_t kb = (uint32_t)(kk * 32) + bcol8;
            #pragma unroll
            for (int cj = 0; cj < 4; cj++) {
                uint32_t off = (uint32_t)((cj * 16 + brow8 + r8) * FK_ROW) + kb;
                uint32_t vh[4];
                ldsm4(vh, bVh + off);
                mma_f16(o[2 * cj],     ph, vh[0], vh[1]);
                mma_f16(o[2 * cj + 1], ph, vh[2], vh[3]);
            }
        }
        __syncthreads();
    }

    // ---- epilogue: O /= l, transpose via smem (fp32), split on write ----
    const uint32_t TH = sb;              // 64 ch x 528B fp32 rows (reuse stages)
    float li0 = 1.f / l0, li1 = 1.f / l1;
    #pragma unroll
    for (int ct = 0; ct < 8; ct++) {
        int c0 = ct * 8 + 2 * tg;
        int row0 = w * 16 + g, row1 = row0 + 8;
        sts_f32(TH + c0 * 528 + row0 * 4,       o[ct][0] * li0);
        sts_f32(TH + (c0 + 1) * 528 + row0 * 4, o[ct][1] * li0);
        sts_f32(TH + c0 * 528 + row1 * 4,       o[ct][2] * li1);
        sts_f32(TH + (c0 + 1) * 528 + row1 * 4, o[ct][3] * li1);
    }
    __syncthreads();
    const int bb = bm / NM, mh = bm - bb * NM;
    const int bt = bb * NT + fr;
    const int p0 = (qt & 1) * 128;
    const int obase = bt * XSTRIDE + mh * 256 + p0;
    #pragma unroll
    for (int it = 0; it < 32; it++) {
        int idx = tid + it * 256;       // 0..8191
        int c = idx >> 7, rr = idx & 127;
        float v = lds_f32(TH + c * 528 + rr * 4);
        __half h, l;
        h_split(v, h, l);
        g_yh[obase + c * 3072 + rr] = h;
        g_yl[obase + c * 3072 + rr] = l;
    }
}

// ---------------- launch ----------------
extern "C" void kernel_launch(void* const* d_in, const int* in_sizes, int n_in,
                              void* d_out, int out_size) {
    const float* x = (const float*)d_in[0];
    const float* wqkv = (const float*)d_in[1];
    const float* wproj = (const float*)d_in[2];
    float* out = (float*)d_out;

    cudaFuncSetAttribute(gemm_f3<0>, cudaFuncAttributeMaxDynamicSharedMemorySize, G_SMEM);
    cudaFuncSetAttribute(gemm_f3<1>, cudaFuncAttributeMaxDynamicSharedMemorySize, G_SMEM);
    cudaFuncSetAttribute(flash_tc, cudaFuncAttributeMaxDynamicSharedMemorySize, FS_TOTAL);

    norm_k<<<C3 + CDIM, 256>>>(wqkv, wproj);
    xsplit<<<(BT * CDIM * 256) / 256, 256>>>(x);
    gemm_f3<0><<<dim3(32, 18), 256, G_SMEM>>>(nullptr, nullptr);
    rope_k<<<(NB * NM * SLEN * 32) / 256, 256>>>();
    flash_tc<<<dim3(16, 24), 256, FS_TOTAL>>>();
    gemm_f3<1><<<dim3(32, 6), 256, G_SMEM>>>(x, out);
}

// round 17
// speedup vs baseline: 2.5793x; 1.3019x over previous
#include <cuda_runtime.h>
#include <cuda_fp16.h>
#include <math.h>
#include <cstdint>

// ---------------------------------------------------------------------------
// VideoAttention: b=2, t=8, C=768, h=w=16 -> hw=256, S=2048, heads=12, c=64
// "One-operand-rounded" fp16 strategy (calibrated R15: each dropped residual
// term costs ~1e-5 final rel err; tolerance 1e-3):
//   GEMMs:  C = (Ah+Al)*Bh      (weights exact via hi/lo, x/y single-rounded)
//   S:      s = (Qh+Ql)*Kh      (q exact via hi/lo, k single-rounded)
//   PV:     o = Ph*Vh           (both single-rounded; R15-measured ~7e-6)
//   K1 norm_k    : EDM2 MP weight norm -> fp16 hi/lo weight planes
//   K2 xsplit    : x -> fp16 hi plane
//   K3 gemm_f3<0>: m16n8k16 HMMA -> q,k fp32; V fp16 [bm][c][s]
//   K4 rope_k    : rotary; k -> fp16
//   K5 flash_tc  : block-causal flash attention, 64-key chunks
//   K6 gemm_f3<1>: proj GEMM + mp_sum residual -> out
// ---------------------------------------------------------------------------

#define NB   2
#define NT   8
#define NM   12
#define HD   64
#define C3   2304
#define CDIM 768
#define SLEN 2048
#define BT   16
#define XSTRIDE 196608   // 768*256

__device__ float g_q[NB * NM * SLEN * HD];
__device__ float g_k[NB * NM * SLEN * HD];
__device__ __half g_kh[NB * NM * SLEN * HD];
__device__ __half g_vh[NB * NM * SLEN * HD];                 // [bm][c][s]
__device__ __half g_wqh[C3 * CDIM],  g_wql[C3 * CDIM];
__device__ __half g_wph[CDIM * CDIM], g_wpl[CDIM * CDIM];
__device__ __half g_xh[BT * CDIM * 256];
__device__ __half g_yh[BT * CDIM * 256];

// ======================= helpers ===================
__device__ __forceinline__ uint32_t smem_to_u32(const void* p) {
    uint32_t a;
    asm("{ .reg .u64 t; cvta.to.shared.u64 t, %1; cvt.u32.u64 %0, t; }" : "=r"(a) : "l"(p));
    return a;
}
__device__ __forceinline__ float lds_f32(uint32_t addr) {
    float v;
    asm volatile("ld.shared.f32 %0, [%1];" : "=f"(v) : "r"(addr));
    return v;
}
__device__ __forceinline__ void sts_f32(uint32_t addr, float v) {
    asm volatile("st.shared.f32 [%0], %1;" :: "r"(addr), "f"(v));
}
__device__ __forceinline__ void sts_u32(uint32_t addr, uint32_t v) {
    asm volatile("st.shared.b32 [%0], %1;" :: "r"(addr), "r"(v));
}
__device__ __forceinline__ void cp16(uint32_t dst, const void* src) {
    asm volatile("cp.async.cg.shared.global [%0], [%1], 16;" :: "r"(dst), "l"(src));
}
#define CP_COMMIT() asm volatile("cp.async.commit_group;" ::: "memory")
#define CP_WAIT(n)  asm volatile("cp.async.wait_group %0;" :: "n"(n) : "memory")

__device__ __forceinline__ void ldsm4(uint32_t (&r)[4], uint32_t addr) {
    asm volatile("ldmatrix.sync.aligned.m8n8.x4.shared.b16 {%0,%1,%2,%3}, [%4];"
                 : "=r"(r[0]), "=r"(r[1]), "=r"(r[2]), "=r"(r[3]) : "r"(addr));
}
__device__ __forceinline__ void ldsm4t(uint32_t (&r)[4], uint32_t addr) {
    asm volatile("ldmatrix.sync.aligned.m8n8.x4.trans.shared.b16 {%0,%1,%2,%3}, [%4];"
                 : "=r"(r[0]), "=r"(r[1]), "=r"(r[2]), "=r"(r[3]) : "r"(addr));
}
__device__ __forceinline__ void mma_f16(float (&d)[4], const uint32_t (&a)[4],
                                        uint32_t b0, uint32_t b1) {
    asm volatile("mma.sync.aligned.m16n8k16.row.col.f32.f16.f16.f32 "
                 "{%0,%1,%2,%3}, {%4,%5,%6,%7}, {%8,%9}, {%0,%1,%2,%3};"
                 : "+f"(d[0]), "+f"(d[1]), "+f"(d[2]), "+f"(d[3])
                 : "r"(a[0]), "r"(a[1]), "r"(a[2]), "r"(a[3]), "r"(b0), "r"(b1));
}
__device__ __forceinline__ void h_split(float a, __half& h, __half& l) {
    h = __float2half_rn(a);
    l = __float2half_rn(a - __half2float(h));
}
__device__ __forceinline__ void h_split_pack(float a, float b, uint32_t& h, uint32_t& l) {
    __half ha, la, hb, lb;
    h_split(a, ha, la);
    h_split(b, hb, lb);
    h = (uint32_t)__half_as_ushort(ha) | ((uint32_t)__half_as_ushort(hb) << 16);
    l = (uint32_t)__half_as_ushort(la) | ((uint32_t)__half_as_ushort(lb) << 16);
}
__device__ __forceinline__ uint32_t h_pack(float a, float b) {
    __half ha = __float2half_rn(a), hb = __float2half_rn(b);
    return (uint32_t)__half_as_ushort(ha) | ((uint32_t)__half_as_ushort(hb) << 16);
}

// ---------------- K1: weight normalization -> fp16 hi/lo planes ------------
__global__ __launch_bounds__(256) void norm_k(const float* __restrict__ wqkv,
                                              const float* __restrict__ wproj) {
    int row = blockIdx.x;
    const float* src;
    __half *dh, *dl;
    if (row < C3) { src = wqkv + row * CDIM; dh = g_wqh + row * CDIM; dl = g_wql + row * CDIM; }
    else { src = wproj + (row - C3) * CDIM; dh = g_wph + (row - C3) * CDIM; dl = g_wpl + (row - C3) * CDIM; }

    float ss = 0.f;
    for (int i = threadIdx.x; i < CDIM; i += 256) { float v = src[i]; ss = fmaf(v, v, ss); }
    #pragma unroll
    for (int off = 16; off; off >>= 1) ss += __shfl_xor_sync(0xffffffffu, ss, off);

    __shared__ float sred[8];
    __shared__ float sscale;
    if ((threadIdx.x & 31) == 0) sred[threadIdx.x >> 5] = ss;
    __syncthreads();
    if (threadIdx.x == 0) {
        float t = 0.f;
        #pragma unroll
        for (int i = 0; i < 8; i++) t += sred[i];
        sscale = 1.0f / (sqrtf(768.0f) * 1e-4f + sqrtf(t));
    }
    __syncthreads();
    float sc = sscale;
    for (int i = threadIdx.x; i < CDIM; i += 256) {
        __half h, l;
        h_split(src[i] * sc, h, l);
        dh[i] = h; dl[i] = l;
    }
}

// ---------------- K2: elementwise x -> fp16 hi plane -----------------------
__global__ __launch_bounds__(256) void xsplit(const float* __restrict__ x) {
    int i = blockIdx.x * 256 + threadIdx.x;
    g_xh[i] = __float2half_rn(x[i]);
}

// ---------------- K3/K6: 2-term HMMA GEMM ((Ah+Al)*Bh), k-chunk 64 ---------
#define GA_ROW 144
#define GB_ROW 272
#define GA_PLANE 18432   // 128*144
#define GB_PLANE 17408   // 64*272
#define G_STAGE  54272   // 2*GA_PLANE + GB_PLANE
#define G_SMEM   108544

template <int EPI>
__global__ __launch_bounds__(256) void gemm_f3(const float* __restrict__ Xres,
                                               float* __restrict__ Out) {
    extern __shared__ char smem[];
    const uint32_t sb = smem_to_u32(smem);
    const int tid = threadIdx.x, wid = tid >> 5, lid = tid & 31;
    const int o0 = blockIdx.y * 128;
    const int n0 = blockIdx.x * 128;
    const int bt = n0 >> 8;
    const int pb = n0 & 255;

    const __half* Awh = (EPI == 0 ? g_wqh : g_wph) + o0 * CDIM;
    const __half* Awl = (EPI == 0 ? g_wql : g_wpl) + o0 * CDIM;
    const __half* Bgh = (EPI == 0 ? g_xh : g_yh) + bt * XSTRIDE + pb;

    float acc[2][8][4];
    #pragma unroll
    for (int mi = 0; mi < 2; mi++)
        #pragma unroll
        for (int ni = 0; ni < 8; ni++)
            #pragma unroll
            for (int d = 0; d < 4; d++) acc[mi][ni][d] = 0.f;

    const int wr = wid & 3, wc = wid >> 2;
    const int g = lid >> 2, tg = lid & 3;
    const int r8 = lid & 7;
    const uint32_t aoff = (uint32_t)((lid & 15) * GA_ROW + ((lid >> 4) & 1) * 16);
    const uint32_t bk8 = (uint32_t)(((lid >> 3) & 1) * 8);
    const uint32_t bn8 = (uint32_t)(((lid >> 4) & 1) * 16);

    auto copy_stage = [&](int st, int kc) {
        uint32_t s0 = sb + st * G_STAGE;
        #pragma unroll
        for (int i = 0; i < 4; i++) {
            int idx = tid + i * 256;
            int row = idx >> 3, u = idx & 7;
            uint32_t dA = s0 + row * GA_ROW + u * 16;
            cp16(dA,            Awh + row * CDIM + kc + u * 8);
            cp16(dA + GA_PLANE, Awl + row * CDIM + kc + u * 8);
            int k = idx >> 4, u2 = idx & 15;
            uint32_t dB = s0 + 2 * GA_PLANE + k * GB_ROW + u2 * 16;
            cp16(dB, Bgh + (kc + k) * 256 + u2 * 8);
        }
        CP_COMMIT();
    };

    copy_stage(0, 0);
    int st = 0;
    for (int kc = 0; kc < CDIM; kc += 64, st ^= 1) {
        if (kc + 64 < CDIM) {
            copy_stage(st ^ 1, kc + 64);
            CP_WAIT(1);
        } else {
            CP_WAIT(0);
        }
        __syncthreads();

        const uint32_t sAh = sb + st * G_STAGE;
        const uint32_t sAl = sAh + GA_PLANE;
        const uint32_t sBh = sAh + 2 * GA_PLANE;
        #pragma unroll
        for (int ks = 0; ks < 4; ks++) {
            uint32_t ah[2][4], al[2][4];
            #pragma unroll
            for (int mi = 0; mi < 2; mi++) {
                uint32_t rbase = (uint32_t)((wr * 32 + mi * 16) * GA_ROW) + aoff + ks * 32;
                ldsm4(ah[mi], sAh + rbase);
                ldsm4(al[mi], sAl + rbase);
            }
            const uint32_t krow = (uint32_t)((ks * 16 + bk8 + r8) * GB_ROW);
            #pragma unroll
            for (int nj = 0; nj < 4; nj++) {
                uint32_t boff = krow + (uint32_t)((wc * 64 + nj * 16) * 2) + bn8;
                uint32_t bh[4];
                ldsm4t(bh, sBh + boff);
                #pragma unroll
                for (int mi = 0; mi < 2; mi++) {
                    mma_f16(acc[mi][2 * nj],     ah[mi], bh[0], bh[1]);
                    mma_f16(acc[mi][2 * nj + 1], ah[mi], bh[2], bh[3]);
                    mma_f16(acc[mi][2 * nj],     al[mi], bh[0], bh[1]);
                    mma_f16(acc[mi][2 * nj + 1], al[mi], bh[2], bh[3]);
                }
            }
        }
        __syncthreads();
    }

    const int cB = tg * 2;

    if (EPI == 0) {
        const int qi = blockIdx.y / 6;
        const int rem0 = o0 - qi * CDIM + wr * 32;
        const int bb = bt >> 3, ti = bt & 7;
        #pragma unroll
        for (int mi = 0; mi < 2; mi++)
            #pragma unroll
            for (int dd = 0; dd < 2; dd++) {
                int rem = rem0 + mi * 16 + g + dd * 8;
                int mh = rem >> 6, cc = rem & 63;
                if (qi < 2) {
                    float* dst = (qi == 0) ? g_q : g_k;
                    int rowbase = ((bb * NM + mh) * SLEN + ti * 256 + pb) * HD + cc;
                    #pragma unroll
                    for (int ni = 0; ni < 8; ni++) {
                        int p = wc * 64 + ni * 8 + cB;
                        dst[rowbase + p * HD]       = acc[mi][ni][dd * 2];
                        dst[rowbase + (p + 1) * HD] = acc[mi][ni][dd * 2 + 1];
                    }
                } else {
                    // V: fp16, transposed layout [bm][c][s]
                    int vbase = ((bb * NM + mh) * HD + cc) * SLEN + ti * 256 + pb;
                    #pragma unroll
                    for (int ni = 0; ni < 8; ni++) {
                        int p = wc * 64 + ni * 8 + cB;
                        g_vh[vbase + p]     = __float2half_rn(acc[mi][ni][dd * 2]);
                        g_vh[vbase + p + 1] = __float2half_rn(acc[mi][ni][dd * 2 + 1]);
                    }
                }
            }
    } else {
        const float c1 = 0.9191450300180578f;   // 0.7 / sqrt(0.58)
        const float c2 = 0.3939192985791676f;   // 0.3 / sqrt(0.58)
        #pragma unroll
        for (int mi = 0; mi < 2; mi++)
            #pragma unroll
            for (int dd = 0; dd < 2; dd++) {
                int o = o0 + wr * 32 + mi * 16 + g + dd * 8;
                int ib = bt * XSTRIDE + o * 256 + pb + wc * 64 + cB;
                #pragma unroll
                for (int ni = 0; ni < 8; ni++) {
                    int idx = ib + ni * 8;
                    Out[idx]     = Xres[idx] * c1 + acc[mi][ni][dd * 2] * c2;
                    Out[idx + 1] = Xres[idx + 1] * c1 + acc[mi][ni][dd * 2 + 1] * c2;
                }
            }
    }
}

// ---------------- K4: RoPE over frame index; K -> fp16 ----------------------
__global__ __launch_bounds__(256) void rope_k() {
    int idx = blockIdx.x * 256 + threadIdx.x;
    int d2 = idx & 31;
    int s = (idx >> 5) & 2047;
    int bm = idx >> 16;
    int ti = s >> 8;
    float ang = (float)ti * __powf(10000.0f, -(float)d2 * (1.0f / 32.0f));
    float sn, cs;
    __sincosf(ang, &sn, &cs);
    int base = (bm * SLEN + s) * HD + d2;
    float q1 = g_q[base], q2 = g_q[base + 32];
    g_q[base]      = q1 * cs - q2 * sn;
    g_q[base + 32] = q1 * sn + q2 * cs;
    float k1 = g_k[base], k2 = g_k[base + 32];
    g_kh[base]      = __float2half_rn(k1 * cs - k2 * sn);
    g_kh[base + 32] = __float2half_rn(k1 * sn + k2 * cs);
}

// ---------------- K5: flash attention: 2-term S, 1-term PV -----------------
// grid (16 q-tiles of 128 rows heavy-first, 24 bm), 256 threads / 8 warps.
// smem stage: Kh ([key 64][144B]) + Vh ([c 64][144B]); 2 stages; + per-warp
// Ph plane (16 x 144B).
#define FK_ROW 144
#define FK_PLANE 9216    // 64*144
#define FS_STAGE 18432   // 2 planes
#define FS_P 36864       // 2 stages
#define FS_TOTAL (FS_P + 8 * 2304)   // 55296

__global__ __launch_bounds__(256) void flash_tc() {
    extern __shared__ char fsm[];
    const uint32_t sb = smem_to_u32(fsm);
    const int tid = threadIdx.x, w = tid >> 5, lid = tid & 31;
    const int g = lid >> 2, tg = lid & 3;
    const int r8 = lid & 7;
    const int qt = 15 - blockIdx.x;      // heavy causal tiles first
    const int bm = blockIdx.y;
    const int s0 = qt * 128;
    const int fr = qt >> 1;
    const int nch = (fr + 1) * 4;        // 64-key chunks

    const uint32_t PSh = sb + FS_P + w * 2304;

    const float* Qg = g_q + (bm * SLEN + s0 + w * 16) * HD;
    const __half* Khg = g_kh + bm * SLEN * HD;
    const __half* Vhg = g_vh + bm * HD * SLEN;   // [c][s]

    const uint32_t brow8 = (uint32_t)(((lid >> 4) & 1) * 8);
    const uint32_t bcol8 = (uint32_t)(((lid >> 3) & 1) * 16);
    const uint32_t poff = (uint32_t)((lid & 15) * FK_ROW + ((lid >> 4) & 1) * 16);

    // register-resident Q fragments (fp16 split, packed pairs)
    uint32_t qh[4][4], ql[4][4];
    #pragma unroll
    for (int ks = 0; ks < 4; ks++) {
        int c0 = ks * 16 + 2 * tg;
        h_split_pack(Qg[g * 64 + c0],           Qg[g * 64 + c0 + 1],       qh[ks][0], ql[ks][0]);
        h_split_pack(Qg[(g + 8) * 64 + c0],     Qg[(g + 8) * 64 + c0 + 1], qh[ks][1], ql[ks][1]);
        h_split_pack(Qg[g * 64 + c0 + 8],       Qg[g * 64 + c0 + 9],       qh[ks][2], ql[ks][2]);
        h_split_pack(Qg[(g + 8) * 64 + c0 + 8], Qg[(g + 8) * 64 + c0 + 9], qh[ks][3], ql[ks][3]);
    }

    float o[8][4];
    #pragma unroll
    for (int ct = 0; ct < 8; ct++)
        #pragma unroll
        for (int d = 0; d < 4; d++) o[ct][d] = 0.f;
    float m0 = -1e30f, m1 = -1e30f, l0 = 0.f, l1 = 0.f;

    auto stage = [&](int st, int k0) {
        uint32_t b0 = sb + st * FS_STAGE;
        #pragma unroll
        for (int i = 0; i < 2; i++) {
            int idx = tid + i * 256;          // 0..511
            int key = idx >> 3, u = idx & 7;
            uint32_t dK = b0 + key * FK_ROW + u * 16;
            cp16(dK, Khg + (k0 + key) * 64 + u * 8);
            uint32_t dV = b0 + FK_PLANE + key * FK_ROW + u * 16;   // key -> channel row
            cp16(dV, Vhg + key * SLEN + k0 + u * 8);
        }
        CP_COMMIT();
    };

    stage(0, 0);
    int st = 0;
    for (int ic = 0; ic < nch; ic++, st ^= 1) {
        if (ic + 1 < nch) {
            stage(st ^ 1, (ic + 1) * 64);
            CP_WAIT(1);
        } else {
            CP_WAIT(0);
        }
        __syncthreads();
        const uint32_t bKh = sb + st * FS_STAGE;
        const uint32_t bVh = bKh + FK_PLANE;

        // ---- S = (Qh+Ql) Kh^T (16 rows x 64 keys per warp) ----
        float s[8][4];
        #pragma unroll
        for (int nt = 0; nt < 8; nt++)
            #pragma unroll
            for (int d = 0; d < 4; d++) s[nt][d] = 0.f;
        #pragma unroll
        for (int ks = 0; ks < 4; ks++) {
            const uint32_t ck = (uint32_t)(ks * 32) + bcol8;
            #pragma unroll
            for (int nj = 0; nj < 4; nj++) {
                uint32_t off = (uint32_t)((nj * 16 + brow8 + r8) * FK_ROW) + ck;
                uint32_t kh[4];
                ldsm4(kh, bKh + off);
                mma_f16(s[2 * nj],     qh[ks], kh[0], kh[1]);
                mma_f16(s[2 * nj + 1], qh[ks], kh[2], kh[3]);
                mma_f16(s[2 * nj],     ql[ks], kh[0], kh[1]);
                mma_f16(s[2 * nj + 1], ql[ks], kh[2], kh[3]);
            }
        }

        // ---- online softmax (rows g, g+8; reduce over the 4 tg lanes) ----
        float mx0 = -1e30f, mx1 = -1e30f;
        #pragma unroll
        for (int nt = 0; nt < 8; nt++) {
            #pragma unroll
            for (int d = 0; d < 4; d++) s[nt][d] *= 0.125f;
            mx0 = fmaxf(mx0, fmaxf(s[nt][0], s[nt][1]));
            mx1 = fmaxf(mx1, fmaxf(s[nt][2], s[nt][3]));
        }
        mx0 = fmaxf(mx0, __shfl_xor_sync(0xffffffffu, mx0, 1));
        mx0 = fmaxf(mx0, __shfl_xor_sync(0xffffffffu, mx0, 2));
        mx1 = fmaxf(mx1, __shfl_xor_sync(0xffffffffu, mx1, 1));
        mx1 = fmaxf(mx1, __shfl_xor_sync(0xffffffffu, mx1, 2));
        float mn0 = fmaxf(m0, mx0), mn1 = fmaxf(m1, mx1);
        float cr0 = __expf(m0 - mn0), cr1 = __expf(m1 - mn1);
        m0 = mn0; m1 = mn1;
        float rs0 = 0.f, rs1 = 0.f;
        #pragma unroll
        for (int nt = 0; nt < 8; nt++) {
            s[nt][0] = __expf(s[nt][0] - mn0);
            s[nt][1] = __expf(s[nt][1] - mn0);
            s[nt][2] = __expf(s[nt][2] - mn1);
            s[nt][3] = __expf(s[nt][3] - mn1);
            rs0 += s[nt][0] + s[nt][1];
            rs1 += s[nt][2] + s[nt][3];
        }
        rs0 += __shfl_xor_sync(0xffffffffu, rs0, 1);
        rs0 += __shfl_xor_sync(0xffffffffu, rs0, 2);
        rs1 += __shfl_xor_sync(0xffffffffu, rs1, 1);
        rs1 += __shfl_xor_sync(0xffffffffu, rs1, 2);
        l0 = l0 * cr0 + rs0;
        l1 = l1 * cr1 + rs1;
        #pragma unroll
        for (int ct = 0; ct < 8; ct++) {
            o[ct][0] *= cr0; o[ct][1] *= cr0;
            o[ct][2] *= cr1; o[ct][3] *= cr1;
        }

        // ---- stage P as packed fp16 (16 rows x 64 keys) ----
        #pragma unroll
        for (int nt = 0; nt < 8; nt++) {
            uint32_t cofs = (uint32_t)(nt * 16 + tg * 4);
            sts_u32(PSh + g * FK_ROW + cofs,       h_pack(s[nt][0], s[nt][1]));
            sts_u32(PSh + (g + 8) * FK_ROW + cofs, h_pack(s[nt][2], s[nt][3]));
        }
        __syncwarp();

        // ---- O += Ph Vh (key k-steps of 16) ----
        #pragma unroll
        for (int kk = 0; kk < 4; kk++) {
            uint32_t ph[4];
            ldsm4(ph, PSh + poff + kk * 32);
            const uint32_t kb = (uint32_t)(kk * 32) + bcol8;
            #pragma unroll
            for (int cj = 0; cj < 4; cj++) {
                uint32_t off = (uint32_t)((cj * 16 + brow8 + r8) * FK_ROW) + kb;
                uint32_t vh[4];
                ldsm4(vh, bVh + off);
                mma_f16(o[2 * cj],     ph, vh[0], vh[1]);
                mma_f16(o[2 * cj + 1], ph, vh[2], vh[3]);
            }
        }
        __syncthreads();
    }

    // ---- epilogue: O /= l, transpose via smem (fp32), fp16 on write ----
    const uint32_t TH = sb;              // 64 ch x 528B fp32 rows (reuse stages)
    float li0 = 1.f / l0, li1 = 1.f / l1;
    #pragma unroll
    for (int ct = 0; ct < 8; ct++) {
        int c0 = ct * 8 + 2 * tg;
        int row0 = w * 16 + g, row1 = row0 + 8;
        sts_f32(TH + c0 * 528 + row0 * 4,       o[ct][0] * li0);
        sts_f32(TH + (c0 + 1) * 528 + row0 * 4, o[ct][1] * li0);
        sts_f32(TH + c0 * 528 + row1 * 4,       o[ct][2] * li1);
        sts_f32(TH + (c0 + 1) * 528 + row1 * 4, o[ct][3] * li1);
    }
    __syncthreads();
    const int bb = bm / NM, mh = bm - bb * NM;
    const int bt = bb * NT + fr;
    const int p0 = (qt & 1) * 128;
    const int obase = bt * XSTRIDE + mh * 256 + p0;
    #pragma unroll
    for (int it = 0; it < 32; it++) {
        int idx = tid + it * 256;       // 0..8191
        int c = idx >> 7, rr = idx & 127;
        g_yh[obase + c * 3072 + rr] = __float2half_rn(lds_f32(TH + c * 528 + rr * 4));
    }
}

// ---------------- launch ----------------
extern "C" void kernel_launch(void* const* d_in, const int* in_sizes, int n_in,
                              void* d_out, int out_size) {
    const float* x = (const float*)d_in[0];
    const float* wqkv = (const float*)d_in[1];
    const float* wproj = (const float*)d_in[2];
    float* out = (float*)d_out;

    cudaFuncSetAttribute(gemm_f3<0>, cudaFuncAttributeMaxDynamicSharedMemorySize, G_SMEM);
    cudaFuncSetAttribute(gemm_f3<1>, cudaFuncAttributeMaxDynamicSharedMemorySize, G_SMEM);
    cudaFuncSetAttribute(flash_tc, cudaFuncAttributeMaxDynamicSharedMemorySize, FS_TOTAL);

    norm_k<<<C3 + CDIM, 256>>>(wqkv, wproj);
    xsplit<<<(BT * CDIM * 256) / 256, 256>>>(x);
    gemm_f3<0><<<dim3(32, 18), 256, G_SMEM>>>(nullptr, nullptr);
    rope_k<<<(NB * NM * SLEN * 32) / 256, 256>>>();
    flash_tc<<<dim3(16, 24), 256, FS_TOTAL>>>();
    gemm_f3<1><<<dim3(32, 6), 256, G_SMEM>>>(x, out);
}